// round 5
// baseline (speedup 1.0000x reference)
#include <cuda_runtime.h>
#include <mma.h>
#include <math.h>

using namespace nvcuda;

#define NFEAT 16
#define EFEAT 8
#define HC    256
#define NCLS  4

static const int MAXN = 50000;
static const int NPAD = 50048;     // padded so 16-row wmma stores never overflow
static const int MAXE = 800000;

typedef wmma::fragment<wmma::matrix_a, 16, 16, 8, wmma::precision::tf32, wmma::row_major> FragA;
typedef wmma::fragment<wmma::matrix_b, 16, 16, 8, wmma::precision::tf32, wmma::row_major> FragB;
typedef wmma::fragment<wmma::accumulator, 16, 16, 8, float> FragC;

__device__ __forceinline__ float tf32r(float v) { return wmma::__float_to_tf32(v); }

// ---------------- scratch ----------------
__device__ float g_x1  [MAXN * 64];
__device__ float g_q   [NPAD * HC];
__device__ float g_k   [NPAD * HC];
__device__ float g_v   [NPAD * HC];
__device__ float g_skip[NPAD * HC];
__device__ float g_g   [MAXN * HC];
__device__ float g_qb  [MAXN * 4];
__device__ float g_e   [MAXE * 64];
__device__ float g_outv[MAXN * HC];
__device__ float g_t   [MAXN * HC];
__device__ float g_suma[MAXN * 4];
__device__ float g_act [MAXN * HC];
__device__ int   g_deg [MAXN];
__device__ int   g_rowptr[MAXN + 1];
__device__ int   g_cursor[MAXN];
__device__ int   g_eid [MAXE];
__device__ int   g_src [MAXE];

// ---------------- CSR build ----------------
__global__ void k_zero_deg(int n) {
    int i = blockIdx.x * blockDim.x + threadIdx.x;
    if (i < n) g_deg[i] = 0;
}
__global__ void k_hist(const int* __restrict__ ei, int e) {
    int i = blockIdx.x * blockDim.x + threadIdx.x;
    if (i < e) atomicAdd(&g_deg[ei[e + i]], 1);
}
__global__ void k_scan(int n) {
    __shared__ int sh[1024];
    __shared__ int s_off;
    int tid = threadIdx.x;
    if (tid == 0) { s_off = 0; g_rowptr[0] = 0; }
    __syncthreads();
    for (int base = 0; base < n; base += 1024) {
        int i = base + tid;
        int val = (i < n) ? g_deg[i] : 0;
        sh[tid] = val;
        __syncthreads();
        for (int off = 1; off < 1024; off <<= 1) {
            int y = (tid >= off) ? sh[tid - off] : 0;
            __syncthreads();
            sh[tid] += y;
            __syncthreads();
        }
        int incl = sh[tid];
        if (i < n) {
            g_rowptr[i + 1] = s_off + incl;
            g_cursor[i]     = s_off + incl - val;
        }
        __syncthreads();
        if (tid == 0) s_off += sh[1023];
        __syncthreads();
    }
}
__global__ void k_scatter(const int* __restrict__ ei, int e) {
    int i = blockIdx.x * blockDim.x + threadIdx.x;
    if (i < e) {
        int dst = ei[e + i];
        int pos = atomicAdd(&g_cursor[dst], 1);
        g_eid[pos] = i;
        g_src[pos] = ei[i];
    }
}

// ---------------- node embed ----------------
__global__ void k_node_embed(const float* __restrict__ x,
                             const float* __restrict__ w00,
                             const float* __restrict__ b00, int n) {
    __shared__ float ws[NFEAT * 64];
    __shared__ float xs[64][NFEAT];
    int tid = threadIdx.x;
    for (int i = tid; i < NFEAT * 64; i += 256) ws[i] = w00[i];
    int nb = blockIdx.x * 64;
    for (int i = tid; i < 64 * NFEAT; i += 256) {
        int nn = nb + i / NFEAT;
        xs[i / NFEAT][i % NFEAT] = (nn < n) ? x[nn * NFEAT + (i % NFEAT)] : 0.f;
    }
    __syncthreads();
    int ln = tid >> 2;
    int node = nb + ln;
    int c0 = (tid & 3) * 16;
    if (node < n) {
        #pragma unroll
        for (int j = 0; j < 16; j++) {
            float acc = __ldg(&b00[c0 + j]);
            #pragma unroll
            for (int i = 0; i < NFEAT; i++) acc += xs[ln][i] * ws[i * 64 + c0 + j];
            g_x1[node * 64 + c0 + j] = fmaxf(acc, 0.f);
        }
    }
}

// ---------------- projections: wmma tf32, bias folded via augmented k -----
__global__ void k_proj(const float* __restrict__ W0, const float* __restrict__ B0,
                       const float* __restrict__ W1, const float* __restrict__ B1,
                       const float* __restrict__ W2, const float* __restrict__ B2,
                       const float* __restrict__ W3, const float* __restrict__ B3,
                       int n) {
    int sel = blockIdx.y;
    const float* W = (sel == 0) ? W0 : (sel == 1) ? W1 : (sel == 2) ? W2 : W3;
    const float* B = (sel == 0) ? B0 : (sel == 1) ? B1 : (sel == 2) ? B2 : B3;
    float* out = (sel == 0) ? g_q : (sel == 1) ? g_k : (sel == 2) ? g_v : g_skip;

    __shared__ float xs[64 * 72];   // [64 nodes][64 feats + 1.0 + 7 zeros]
    __shared__ float bs[8 * 256];   // row 0 = bias, rows 1..7 = 0

    int tid = threadIdx.x;
    int nb = blockIdx.x * 64;
    for (int i = tid; i < 64 * 72; i += 256) {
        int r = i / 72, c = i - r * 72;
        float v;
        if (c < 64) {
            int node = nb + r;
            v = (node < n) ? tf32r(__ldg(&g_x1[node * 64 + c])) : 0.f;
        } else {
            v = (c == 64) ? 1.0f : 0.f;
        }
        xs[i] = v;
    }
    for (int i = tid; i < 2048; i += 256)
        bs[i] = (i < 256) ? tf32r(__ldg(&B[i])) : 0.f;
    __syncthreads();

    int w = tid >> 5;
    int rt = w >> 1;        // row tile (4 of 16 rows)
    int ch = w & 1;         // col half (128 cols)

    FragA a[9];
    #pragma unroll
    for (int k = 0; k < 9; k++)
        wmma::load_matrix_sync(a[k], &xs[rt * 16 * 72 + k * 8], 72);

    #pragma unroll
    for (int cp = 0; cp < 4; cp++) {
        int c0 = ch * 128 + cp * 32;
        FragC acc0, acc1;
        wmma::fill_fragment(acc0, 0.f);
        wmma::fill_fragment(acc1, 0.f);
        #pragma unroll
        for (int k = 0; k < 9; k++) {
            const float* bp = (k < 8) ? &W[k * 8 * HC + c0] : &bs[c0];
            FragB b0, b1;
            wmma::load_matrix_sync(b0, bp, HC);
            wmma::load_matrix_sync(b1, bp + 16, HC);
            #pragma unroll
            for (int t = 0; t < b0.num_elements; t++) {
                b0.x[t] = tf32r(b0.x[t]);
                b1.x[t] = tf32r(b1.x[t]);
            }
            wmma::mma_sync(acc0, a[k], b0, acc0);
            wmma::mma_sync(acc1, a[k], b1, acc1);
        }
        float* op = &out[(nb + rt * 16) * HC + c0];
        wmma::store_matrix_sync(op, acc0, HC, wmma::mem_row_major);
        wmma::store_matrix_sync(op + 16, acc1, HC, wmma::mem_row_major);
    }
}

// ---------------- g = per-head wedge^T @ q ; qb = q . bedge ----------------
__global__ void k_g(const float* __restrict__ wedge, const float* __restrict__ bedge,
                    int n) {
    __shared__ float qs[32 * HC];
    int tid = threadIdx.x;
    int nb = blockIdx.x * 32;
    for (int i = tid; i < 2048; i += 256) {
        int row = i >> 6, q4 = i & 63;
        int node = nb + row;
        float4 v = make_float4(0.f, 0.f, 0.f, 0.f);
        if (node < n) v = *(const float4*)&g_q[node * HC + q4 * 4];
        *(float4*)&qs[row * HC + q4 * 4] = v;
    }
    __syncthreads();
    int h = tid >> 6, ii = tid & 63;
    float acc[32];
    #pragma unroll
    for (int m = 0; m < 32; m++) acc[m] = 0.f;
    for (int c = 0; c < 64; c++) {
        float w = __ldg(&wedge[ii * HC + h * 64 + c]);
        #pragma unroll
        for (int m = 0; m < 32; m++) acc[m] += qs[m * HC + h * 64 + c] * w;
    }
    #pragma unroll
    for (int m = 0; m < 32; m++) {
        int nn = nb + m;
        if (nn < n) g_g[nn * HC + tid] = acc[m];
    }
    if (tid < 128) {
        int m = tid >> 2, h2 = tid & 3;
        int nn = nb + m;
        if (nn < n) {
            float s = 0.f;
            for (int c = 0; c < 64; c++) s += qs[m * HC + h2 * 64 + c] * __ldg(&bedge[h2 * 64 + c]);
            g_qb[nn * 4 + h2] = s;
        }
    }
}

// ---------------- edge MLP: wmma tf32, 128 edges/block ---------------------
// smem layout (floats):
//   es  [128][16]  : 8 attrs + 1.0 + 7 zeros          @ 0     (2048)
//   w1b [16][64]   : we1 rows 0..7, be1 row 8, 0s      @ 2048  (1024)
//   w2b [72][64]   : we2 rows 0..63, be2 row 64, 0s    @ 3072  (4608)
//   w3b [72][64]                                       @ 7680  (4608)
//   h1  [128][72]  : hidden + bias col                 @ 12288 (9216)
//   h2  [128][72]                                      @ 21504 (9216)
__global__ void k_edgemlp(const float* __restrict__ eattr,
                          const float* __restrict__ we1, const float* __restrict__ be1,
                          const float* __restrict__ we2, const float* __restrict__ be2,
                          const float* __restrict__ we3, const float* __restrict__ be3,
                          int e) {
    extern __shared__ float sm[];
    float* es  = sm;
    float* w1b = sm + 2048;
    float* w2b = sm + 3072;
    float* w3b = sm + 7680;
    float* h1  = sm + 12288;
    float* h2  = sm + 21504;

    int tid = threadIdx.x;
    int pb = blockIdx.x * 128;

    for (int i = tid; i < 1024; i += 256) {
        int r = i >> 6, c = i & 63;
        float v = (r < 8) ? __ldg(&we1[r * 64 + c]) : ((r == 8) ? __ldg(&be1[c]) : 0.f);
        w1b[i] = tf32r(v);
    }
    for (int i = tid; i < 4608; i += 256) {
        int r = i >> 6, c = i & 63;
        w2b[i] = tf32r((r < 64) ? __ldg(&we2[r * 64 + c]) : ((r == 64) ? __ldg(&be2[c]) : 0.f));
        w3b[i] = tf32r((r < 64) ? __ldg(&we3[r * 64 + c]) : ((r == 64) ? __ldg(&be3[c]) : 0.f));
    }
    for (int i = tid; i < 2048; i += 256) {
        int r = i >> 4, c = i & 15;
        float v;
        if (c < 8) {
            int p = pb + r;
            if (p < e) {
                int id = g_eid[p];
                v = tf32r(__ldg(&eattr[id * 8 + c]));
            } else v = 0.f;
        } else {
            v = (c == 8) ? 1.0f : 0.f;
        }
        es[i] = v;
    }
    // bias columns of h1/h2 (written once; wmma stores only touch cols 0..63)
    for (int i = tid; i < 1024; i += 256) {
        int r = i >> 3, c = 64 + (i & 7);
        float v = (c == 64) ? 1.0f : 0.f;
        h1[r * 72 + c] = v;
        h2[r * 72 + c] = v;
    }
    __syncthreads();

    int w = tid >> 5;        // warp -> 16-row tile

    // ---- layer 1 (k=16: 8 attrs + bias) ----
    {
        FragA a0, a1;
        wmma::load_matrix_sync(a0, &es[w * 16 * 16 + 0], 16);
        wmma::load_matrix_sync(a1, &es[w * 16 * 16 + 8], 16);
        #pragma unroll
        for (int cp = 0; cp < 2; cp++) {
            int c0 = cp * 32;
            FragC acc0, acc1;
            wmma::fill_fragment(acc0, 0.f);
            wmma::fill_fragment(acc1, 0.f);
            FragB b;
            wmma::load_matrix_sync(b, &w1b[0 * 64 + c0], 64);
            wmma::mma_sync(acc0, a0, b, acc0);
            wmma::load_matrix_sync(b, &w1b[0 * 64 + c0 + 16], 64);
            wmma::mma_sync(acc1, a0, b, acc1);
            wmma::load_matrix_sync(b, &w1b[8 * 64 + c0], 64);
            wmma::mma_sync(acc0, a1, b, acc0);
            wmma::load_matrix_sync(b, &w1b[8 * 64 + c0 + 16], 64);
            wmma::mma_sync(acc1, a1, b, acc1);
            wmma::store_matrix_sync(&h1[w * 16 * 72 + c0], acc0, 72, wmma::mem_row_major);
            wmma::store_matrix_sync(&h1[w * 16 * 72 + c0 + 16], acc1, 72, wmma::mem_row_major);
        }
    }
    __syncthreads();
    for (int i = tid; i < 8192; i += 256) {
        int r = i >> 6, c = i & 63;
        h1[r * 72 + c] = tf32r(fmaxf(h1[r * 72 + c], 0.f));
    }
    __syncthreads();

    // ---- layer 2 (k=72) ----
    {
        FragA a[9];
        #pragma unroll
        for (int k = 0; k < 9; k++)
            wmma::load_matrix_sync(a[k], &h1[w * 16 * 72 + k * 8], 72);
        #pragma unroll
        for (int cp = 0; cp < 2; cp++) {
            int c0 = cp * 32;
            FragC acc0, acc1;
            wmma::fill_fragment(acc0, 0.f);
            wmma::fill_fragment(acc1, 0.f);
            #pragma unroll
            for (int k = 0; k < 9; k++) {
                FragB b0, b1;
                wmma::load_matrix_sync(b0, &w2b[k * 8 * 64 + c0], 64);
                wmma::load_matrix_sync(b1, &w2b[k * 8 * 64 + c0 + 16], 64);
                wmma::mma_sync(acc0, a[k], b0, acc0);
                wmma::mma_sync(acc1, a[k], b1, acc1);
            }
            wmma::store_matrix_sync(&h2[w * 16 * 72 + c0], acc0, 72, wmma::mem_row_major);
            wmma::store_matrix_sync(&h2[w * 16 * 72 + c0 + 16], acc1, 72, wmma::mem_row_major);
        }
    }
    __syncthreads();
    for (int i = tid; i < 8192; i += 256) {
        int r = i >> 6, c = i & 63;
        h2[r * 72 + c] = tf32r(fmaxf(h2[r * 72 + c], 0.f));
    }
    __syncthreads();

    // ---- layer 3 (k=72) -> g_e (PRE-relu; relu applied in k_attn) ----
    {
        FragA a[9];
        #pragma unroll
        for (int k = 0; k < 9; k++)
            wmma::load_matrix_sync(a[k], &h2[w * 16 * 72 + k * 8], 72);
        #pragma unroll
        for (int cp = 0; cp < 2; cp++) {
            int c0 = cp * 32;
            FragC acc0, acc1;
            wmma::fill_fragment(acc0, 0.f);
            wmma::fill_fragment(acc1, 0.f);
            #pragma unroll
            for (int k = 0; k < 9; k++) {
                FragB b0, b1;
                wmma::load_matrix_sync(b0, &w3b[k * 8 * 64 + c0], 64);
                wmma::load_matrix_sync(b1, &w3b[k * 8 * 64 + c0 + 16], 64);
                wmma::mma_sync(acc0, a[k], b0, acc0);
                wmma::mma_sync(acc1, a[k], b1, acc1);
            }
            float* op = &g_e[(pb + w * 16) * 64 + c0];
            wmma::store_matrix_sync(op, acc0, 64, wmma::mem_row_major);
            wmma::store_matrix_sync(op + 16, acc1, 64, wmma::mem_row_major);
        }
    }
}

// ---------------- attention: warp per node (relu applied to e loads) -------
__device__ __forceinline__ float dot4(float4 a, float4 b) {
    return a.x * b.x + a.y * b.y + a.z * b.z + a.w * b.w;
}
__device__ __forceinline__ float4 relu4(float4 a) {
    return make_float4(fmaxf(a.x, 0.f), fmaxf(a.y, 0.f), fmaxf(a.z, 0.f), fmaxf(a.w, 0.f));
}

__global__ void k_attn(int n) {
    int gw = (blockIdx.x * blockDim.x + threadIdx.x) >> 5;
    int lane = threadIdx.x & 31;
    if (gw >= n) return;
    int node = gw;
    int beg = g_rowptr[node], end = g_rowptr[node + 1];

    int h = lane >> 3;
    int c8 = (lane & 7) * 8;
    int chan = h * 64 + c8;

    float4 q0 = *(const float4*)&g_q[node * HC + chan];
    float4 q1 = *(const float4*)&g_q[node * HC + chan + 4];
    float4 gg0 = *(const float4*)&g_g[node * HC + chan];
    float4 gg1 = *(const float4*)&g_g[node * HC + chan + 4];
    float qb = g_qb[node * 4 + h];

    float s = 0.f;
    float4 av0 = {0,0,0,0}, av1 = {0,0,0,0};
    float4 at0 = {0,0,0,0}, at1 = {0,0,0,0};

    int p = beg;
    for (; p + 2 <= end; p += 2) {
        int srcA = g_src[p], srcB = g_src[p + 1];
        float4 kA0 = *(const float4*)&g_k[srcA * HC + chan];
        float4 kA1 = *(const float4*)&g_k[srcA * HC + chan + 4];
        float4 eA0 = relu4(*(const float4*)&g_e[p * 64 + c8]);
        float4 eA1 = relu4(*(const float4*)&g_e[p * 64 + c8 + 4]);
        float4 kB0 = *(const float4*)&g_k[srcB * HC + chan];
        float4 kB1 = *(const float4*)&g_k[srcB * HC + chan + 4];
        float4 eB0 = relu4(*(const float4*)&g_e[(p + 1) * 64 + c8]);
        float4 eB1 = relu4(*(const float4*)&g_e[(p + 1) * 64 + c8 + 4]);

        float dA = dot4(q0, kA0) + dot4(q1, kA1) + dot4(gg0, eA0) + dot4(gg1, eA1);
        float dB = dot4(q0, kB0) + dot4(q1, kB1) + dot4(gg0, eB0) + dot4(gg1, eB1);
        dA += __shfl_xor_sync(0xffffffffu, dA, 1);
        dB += __shfl_xor_sync(0xffffffffu, dB, 1);
        dA += __shfl_xor_sync(0xffffffffu, dA, 2);
        dB += __shfl_xor_sync(0xffffffffu, dB, 2);
        dA += __shfl_xor_sync(0xffffffffu, dA, 4);
        dB += __shfl_xor_sync(0xffffffffu, dB, 4);
        float peA = __expf((dA + qb) * 0.125f);
        float peB = __expf((dB + qb) * 0.125f);
        s += peA + peB;

        float4 vA0 = *(const float4*)&g_v[srcA * HC + chan];
        float4 vA1 = *(const float4*)&g_v[srcA * HC + chan + 4];
        float4 vB0 = *(const float4*)&g_v[srcB * HC + chan];
        float4 vB1 = *(const float4*)&g_v[srcB * HC + chan + 4];

        av0.x += peA * vA0.x + peB * vB0.x;  av0.y += peA * vA0.y + peB * vB0.y;
        av0.z += peA * vA0.z + peB * vB0.z;  av0.w += peA * vA0.w + peB * vB0.w;
        av1.x += peA * vA1.x + peB * vB1.x;  av1.y += peA * vA1.y + peB * vB1.y;
        av1.z += peA * vA1.z + peB * vB1.z;  av1.w += peA * vA1.w + peB * vB1.w;
        at0.x += peA * eA0.x + peB * eB0.x;  at0.y += peA * eA0.y + peB * eB0.y;
        at0.z += peA * eA0.z + peB * eB0.z;  at0.w += peA * eA0.w + peB * eB0.w;
        at1.x += peA * eA1.x + peB * eB1.x;  at1.y += peA * eA1.y + peB * eB1.y;
        at1.z += peA * eA1.z + peB * eB1.z;  at1.w += peA * eA1.w + peB * eB1.w;
    }
    if (p < end) {
        int src = g_src[p];
        float4 k0 = *(const float4*)&g_k[src * HC + chan];
        float4 k1 = *(const float4*)&g_k[src * HC + chan + 4];
        float4 e0 = relu4(*(const float4*)&g_e[p * 64 + c8]);
        float4 e1 = relu4(*(const float4*)&g_e[p * 64 + c8 + 4]);
        float d = dot4(q0, k0) + dot4(q1, k1) + dot4(gg0, e0) + dot4(gg1, e1);
        d += __shfl_xor_sync(0xffffffffu, d, 1);
        d += __shfl_xor_sync(0xffffffffu, d, 2);
        d += __shfl_xor_sync(0xffffffffu, d, 4);
        float pe = __expf((d + qb) * 0.125f);
        s += pe;
        float4 v0 = *(const float4*)&g_v[src * HC + chan];
        float4 v1 = *(const float4*)&g_v[src * HC + chan + 4];
        av0.x += pe * v0.x; av0.y += pe * v0.y; av0.z += pe * v0.z; av0.w += pe * v0.w;
        av1.x += pe * v1.x; av1.y += pe * v1.y; av1.z += pe * v1.z; av1.w += pe * v1.w;
        at0.x += pe * e0.x; at0.y += pe * e0.y; at0.z += pe * e0.z; at0.w += pe * e0.w;
        at1.x += pe * e1.x; at1.y += pe * e1.y; at1.z += pe * e1.z; at1.w += pe * e1.w;
    }

    float sinv = 1.f / (s + 1e-16f);
    float4 o0 = {av0.x * sinv, av0.y * sinv, av0.z * sinv, av0.w * sinv};
    float4 o1 = {av1.x * sinv, av1.y * sinv, av1.z * sinv, av1.w * sinv};
    float4 t0 = {at0.x * sinv, at0.y * sinv, at0.z * sinv, at0.w * sinv};
    float4 t1 = {at1.x * sinv, at1.y * sinv, at1.z * sinv, at1.w * sinv};
    *(float4*)&g_outv[node * HC + chan]     = o0;
    *(float4*)&g_outv[node * HC + chan + 4] = o1;
    *(float4*)&g_t   [node * HC + chan]     = t0;
    *(float4*)&g_t   [node * HC + chan + 4] = t1;
    if ((lane & 7) == 0) g_suma[node * 4 + h] = s * sinv;
}

// ---------------- epilogue 1 ----------------
__global__ void k_post(const float* __restrict__ wedge, const float* __restrict__ bedge,
                       const float* __restrict__ ln_g, const float* __restrict__ ln_b,
                       int n) {
    __shared__ float ts[16][HC];
    __shared__ float os[16][HC];
    int tid = threadIdx.x;
    int nb = blockIdx.x * 16;
    for (int i = tid; i < 16 * HC; i += 256) {
        int nn = nb + i / HC;
        ts[i / HC][i % HC] = (nn < n) ? g_t[nn * HC + (i % HC)] : 0.f;
    }
    __syncthreads();
    int h = tid >> 6;
    float acc[16];
    #pragma unroll
    for (int m = 0; m < 16; m++) acc[m] = 0.f;
    for (int i = 0; i < 64; i++) {
        float w = __ldg(&wedge[i * HC + tid]);
        #pragma unroll
        for (int m = 0; m < 16; m++) acc[m] += ts[m][h * 64 + i] * w;
    }
    float be = __ldg(&bedge[tid]);
    #pragma unroll
    for (int m = 0; m < 16; m++) {
        int nn = nb + m;
        if (nn < n) {
            float val = g_outv[nn * HC + tid] + g_suma[nn * 4 + h] * be
                      + g_skip[nn * HC + tid] + acc[m];
            os[m][tid] = val;
        }
    }
    __syncthreads();
    int wid = tid >> 5, lane = tid & 31;
    for (int m = wid; m < 16; m += 8) {
        int nn = nb + m;
        if (nn >= n) continue;
        float sum = 0.f, sq = 0.f;
        #pragma unroll
        for (int u = 0; u < 8; u++) {
            float v = os[m][u * 32 + lane];
            sum += v; sq += v * v;
        }
        #pragma unroll
        for (int off = 16; off; off >>= 1) {
            sum += __shfl_xor_sync(0xffffffffu, sum, off);
            sq  += __shfl_xor_sync(0xffffffffu, sq,  off);
        }
        float mu = sum * (1.f / 256.f);
        float var = sq * (1.f / 256.f) - mu * mu;
        float rs = rsqrtf(var + 1e-5f);
        #pragma unroll
        for (int u = 0; u < 8; u++) {
            int j = u * 32 + lane;
            float v = (os[m][j] - mu) * rs * __ldg(&ln_g[j]) + __ldg(&ln_b[j]);
            g_act[nn * HC + j] = fmaxf(v, 0.f);
        }
    }
}

// ---------------- epilogue 2 ----------------
__global__ void k_head(const float* __restrict__ w1, const float* __restrict__ b1,
                       const float* __restrict__ w2, const float* __restrict__ b2,
                       float* __restrict__ out, int n) {
    __shared__ float as[16][HC];
    __shared__ float hs[16][128];
    __shared__ float ls[16][NCLS];
    int tid = threadIdx.x;
    int nb = blockIdx.x * 16;
    for (int i = tid; i < 16 * HC; i += 128) {
        int nn = nb + i / HC;
        as[i / HC][i % HC] = (nn < n) ? g_act[nn * HC + (i % HC)] : 0.f;
    }
    __syncthreads();
    float acc[16];
    float bb = __ldg(&b1[tid]);
    #pragma unroll
    for (int m = 0; m < 16; m++) acc[m] = bb;
    for (int i = 0; i < HC; i++) {
        float w = __ldg(&w1[i * 128 + tid]);
        #pragma unroll
        for (int m = 0; m < 16; m++) acc[m] += as[m][i] * w;
    }
    #pragma unroll
    for (int m = 0; m < 16; m++) hs[m][tid] = fmaxf(acc[m], 0.f);
    __syncthreads();
    if (tid < 64) {
        int m = tid >> 2, c = tid & 3;
        float a = __ldg(&b2[c]);
        for (int i = 0; i < 128; i++) a += hs[m][i] * __ldg(&w2[i * NCLS + c]);
        ls[m][c] = a;
    }
    __syncthreads();
    if (tid < 16) {
        int nn = nb + tid;
        if (nn < n) {
            float l0 = ls[tid][0], l1 = ls[tid][1], l2 = ls[tid][2], l3 = ls[tid][3];
            float mx = fmaxf(fmaxf(l0, l1), fmaxf(l2, l3));
            float se = expf(l0 - mx) + expf(l1 - mx) + expf(l2 - mx) + expf(l3 - mx);
            float lse = mx + logf(se);
            out[nn * NCLS + 0] = l0 - lse;
            out[nn * NCLS + 1] = l1 - lse;
            out[nn * NCLS + 2] = l2 - lse;
            out[nn * NCLS + 3] = l3 - lse;
        }
    }
}

// ---------------- launcher ----------------
extern "C" void kernel_launch(void* const* d_in, const int* in_sizes, int n_in,
                              void* d_out, int out_size) {
    const float* x     = (const float*)d_in[0];
    const int*   ei    = (const int*)  d_in[1];
    const float* eattr = (const float*)d_in[2];
    const float* w00   = (const float*)d_in[3];
    const float* b00   = (const float*)d_in[4];
    const float* we1   = (const float*)d_in[5];
    const float* be1   = (const float*)d_in[6];
    const float* we2   = (const float*)d_in[7];
    const float* be2   = (const float*)d_in[8];
    const float* we3   = (const float*)d_in[9];
    const float* be3   = (const float*)d_in[10];
    const float* wq    = (const float*)d_in[11];
    const float* bq    = (const float*)d_in[12];
    const float* wk    = (const float*)d_in[13];
    const float* bk    = (const float*)d_in[14];
    const float* wv    = (const float*)d_in[15];
    const float* bv    = (const float*)d_in[16];
    const float* wedge = (const float*)d_in[17];
    const float* bedge = (const float*)d_in[18];
    const float* wskip = (const float*)d_in[19];
    const float* bskip = (const float*)d_in[20];
    const float* ln_g  = (const float*)d_in[21];
    const float* ln_b  = (const float*)d_in[22];
    const float* w1    = (const float*)d_in[23];
    const float* b1    = (const float*)d_in[24];
    const float* w2    = (const float*)d_in[25];
    const float* b2    = (const float*)d_in[26];
    float* out = (float*)d_out;

    int n = in_sizes[0] / NFEAT;
    int e = in_sizes[1] / 2;

    static const int EDGE_SMEM = 30720 * 4;   // 122880 bytes
    cudaFuncSetAttribute(k_edgemlp, cudaFuncAttributeMaxDynamicSharedMemorySize, EDGE_SMEM);

    k_zero_deg<<<(n + 255) / 256, 256>>>(n);
    k_hist<<<(e + 255) / 256, 256>>>(ei, e);
    k_scan<<<1, 1024>>>(n);
    k_scatter<<<(e + 255) / 256, 256>>>(ei, e);

    k_node_embed<<<(n + 63) / 64, 256>>>(x, w00, b00, n);
    {
        dim3 grid((n + 63) / 64, 4);
        k_proj<<<grid, 256>>>(wq, bq, wk, bk, wv, bv, wskip, bskip, n);
    }
    k_g<<<(n + 31) / 32, 256>>>(wedge, bedge, n);

    k_edgemlp<<<(e + 127) / 128, 256, EDGE_SMEM>>>(eattr, we1, be1, we2, be2, we3, be3, e);

    k_attn<<<(n + 7) / 8, 256>>>(n);

    k_post<<<(n + 15) / 16, 256>>>(wedge, bedge, ln_g, ln_b, n);
    k_head<<<(n + 15) / 16, 128>>>(w1, b1, w2, b2, out, n);
}

// round 6
// speedup vs baseline: 1.3137x; 1.3137x over previous
#include <cuda_runtime.h>
#include <cuda_fp16.h>
#include <mma.h>
#include <math.h>

using namespace nvcuda;

#define NFEAT 16
#define EFEAT 8
#define HC    256
#define NCLS  4

static const int MAXN = 50000;
static const int NPAD = 50048;     // padded so 16-row wmma stores never overflow
static const int MAXE = 800000;

typedef wmma::fragment<wmma::matrix_a, 16, 16, 16, __half, wmma::row_major> HFragA;
typedef wmma::fragment<wmma::matrix_b, 16, 16, 16, __half, wmma::row_major> HFragB;
typedef wmma::fragment<wmma::accumulator, 16, 16, 16, float> HFragC;

// ---------------- scratch ----------------
__device__ float g_x1  [MAXN * 64];
__device__ float g_q   [NPAD * HC];
__device__ float g_k   [NPAD * HC];
__device__ float g_v   [NPAD * HC];
__device__ float g_skip[NPAD * HC];
__device__ float g_g   [MAXN * HC];
__device__ float g_qb  [MAXN * 4];
__device__ float g_e   [MAXE * 64];
__device__ float g_outv[MAXN * HC];
__device__ float g_t   [MAXN * HC];
__device__ float g_suma[MAXN * 4];
__device__ float g_act [MAXN * HC];
__device__ int   g_deg [MAXN];
__device__ int   g_rowptr[MAXN + 1];
__device__ int   g_cursor[MAXN];
__device__ int   g_eid [MAXE];
__device__ int   g_src [MAXE];

// ---------------- CSR build ----------------
__global__ void k_zero_deg(int n) {
    int i = blockIdx.x * blockDim.x + threadIdx.x;
    if (i < n) g_deg[i] = 0;
}
__global__ void k_hist(const int* __restrict__ ei, int e) {
    int i = blockIdx.x * blockDim.x + threadIdx.x;
    if (i < e) atomicAdd(&g_deg[ei[e + i]], 1);
}
__global__ void k_scan(int n) {
    __shared__ int sh[1024];
    __shared__ int s_off;
    int tid = threadIdx.x;
    if (tid == 0) { s_off = 0; g_rowptr[0] = 0; }
    __syncthreads();
    for (int base = 0; base < n; base += 1024) {
        int i = base + tid;
        int val = (i < n) ? g_deg[i] : 0;
        sh[tid] = val;
        __syncthreads();
        for (int off = 1; off < 1024; off <<= 1) {
            int y = (tid >= off) ? sh[tid - off] : 0;
            __syncthreads();
            sh[tid] += y;
            __syncthreads();
        }
        int incl = sh[tid];
        if (i < n) {
            g_rowptr[i + 1] = s_off + incl;
            g_cursor[i]     = s_off + incl - val;
        }
        __syncthreads();
        if (tid == 0) s_off += sh[1023];
        __syncthreads();
    }
}
__global__ void k_scatter(const int* __restrict__ ei, int e) {
    int i = blockIdx.x * blockDim.x + threadIdx.x;
    if (i < e) {
        int dst = ei[e + i];
        int pos = atomicAdd(&g_cursor[dst], 1);
        g_eid[pos] = i;
        g_src[pos] = ei[i];
    }
}

// ---------------- node embed ----------------
__global__ void k_node_embed(const float* __restrict__ x,
                             const float* __restrict__ w00,
                             const float* __restrict__ b00, int n) {
    __shared__ float ws[NFEAT * 64];
    __shared__ float xs[64][NFEAT];
    int tid = threadIdx.x;
    for (int i = tid; i < NFEAT * 64; i += 256) ws[i] = w00[i];
    int nb = blockIdx.x * 64;
    for (int i = tid; i < 64 * NFEAT; i += 256) {
        int nn = nb + i / NFEAT;
        xs[i / NFEAT][i % NFEAT] = (nn < n) ? x[nn * NFEAT + (i % NFEAT)] : 0.f;
    }
    __syncthreads();
    int ln = tid >> 2;
    int node = nb + ln;
    int c0 = (tid & 3) * 16;
    if (node < n) {
        #pragma unroll
        for (int j = 0; j < 16; j++) {
            float acc = __ldg(&b00[c0 + j]);
            #pragma unroll
            for (int i = 0; i < NFEAT; i++) acc += xs[ln][i] * ws[i * 64 + c0 + j];
            g_x1[node * 64 + c0 + j] = fmaxf(acc, 0.f);
        }
    }
}

// ---------------- projections: fp16 wmma, bias via augmented k ------------
// smem (halves): xsh [64][88]  (64 feats, col64=1, rest 0)      @0      5632
//                wsh [80][264] (rows0..63=W, row64=B, rest 0)   @5632   21120
__global__ void k_proj(const float* __restrict__ W0, const float* __restrict__ B0,
                       const float* __restrict__ W1, const float* __restrict__ B1,
                       const float* __restrict__ W2, const float* __restrict__ B2,
                       const float* __restrict__ W3, const float* __restrict__ B3,
                       int n) {
    int sel = blockIdx.y;
    const float* W = (sel == 0) ? W0 : (sel == 1) ? W1 : (sel == 2) ? W2 : W3;
    const float* B = (sel == 0) ? B0 : (sel == 1) ? B1 : (sel == 2) ? B2 : B3;
    float* out = (sel == 0) ? g_q : (sel == 1) ? g_k : (sel == 2) ? g_v : g_skip;

    extern __shared__ __half smh[];
    __half* xsh = smh;            // stride 88
    __half* wsh = smh + 5632;     // stride 264

    int tid = threadIdx.x;
    int nb = blockIdx.x * 64;

    for (int i = tid; i < 64 * 88; i += 256) {
        int r = i / 88, c = i - r * 88;
        float v = 0.f;
        if (c < 64) {
            int node = nb + r;
            if (node < n) v = __ldg(&g_x1[node * 64 + c]);
        } else if (c == 64) v = 1.0f;
        xsh[i] = __float2half(v);
    }
    for (int i = tid; i < 80 * 264; i += 256) {
        int r = i / 264, c = i - r * 264;
        float v = 0.f;
        if (c < 256) {
            if (r < 64) v = __ldg(&W[r * 256 + c]);
            else if (r == 64) v = __ldg(&B[c]);
        }
        wsh[i] = __float2half(v);
    }
    __syncthreads();

    int w = tid >> 5;
    int rt = w >> 1;        // 4 row tiles of 16
    int ch = w & 1;         // 128-col half

    HFragA a[5];
    #pragma unroll
    for (int k = 0; k < 5; k++)
        wmma::load_matrix_sync(a[k], &xsh[rt * 16 * 88 + k * 16], 88);

    #pragma unroll
    for (int nf = 0; nf < 8; nf++) {
        int c0 = ch * 128 + nf * 16;
        HFragC acc;
        wmma::fill_fragment(acc, 0.f);
        #pragma unroll
        for (int k = 0; k < 5; k++) {
            HFragB b;
            wmma::load_matrix_sync(b, &wsh[k * 16 * 264 + c0], 264);
            wmma::mma_sync(acc, a[k], b, acc);
        }
        wmma::store_matrix_sync(&out[(nb + rt * 16) * HC + c0], acc, HC, wmma::mem_row_major);
    }
}

// ---------------- g = per-head wedge^T @ q ; qb = q . bedge ----------------
__global__ void k_g(const float* __restrict__ wedge, const float* __restrict__ bedge,
                    int n) {
    __shared__ float qs[32 * HC];
    int tid = threadIdx.x;
    int nb = blockIdx.x * 32;
    for (int i = tid; i < 2048; i += 256) {
        int row = i >> 6, q4 = i & 63;
        int node = nb + row;
        float4 v = make_float4(0.f, 0.f, 0.f, 0.f);
        if (node < n) v = *(const float4*)&g_q[node * HC + q4 * 4];
        *(float4*)&qs[row * HC + q4 * 4] = v;
    }
    __syncthreads();
    int h = tid >> 6, ii = tid & 63;
    float acc[32];
    #pragma unroll
    for (int m = 0; m < 32; m++) acc[m] = 0.f;
    for (int c = 0; c < 64; c++) {
        float w = __ldg(&wedge[ii * HC + h * 64 + c]);
        #pragma unroll
        for (int m = 0; m < 32; m++) acc[m] += qs[m * HC + h * 64 + c] * w;
    }
    #pragma unroll
    for (int m = 0; m < 32; m++) {
        int nn = nb + m;
        if (nn < n) g_g[nn * HC + tid] = acc[m];
    }
    if (tid < 128) {
        int m = tid >> 2, h2 = tid & 3;
        int nn = nb + m;
        if (nn < n) {
            float s = 0.f;
            for (int c = 0; c < 64; c++) s += qs[m * HC + h2 * 64 + c] * __ldg(&bedge[h2 * 64 + c]);
            g_qb[nn * 4 + h2] = s;
        }
    }
}

// ---------------- edge MLP: fp16 wmma, 128 edges/block ---------------------
// smem halves: es   [128][16]   @0      2048
//              w1b  [16][72]    @2048   1152
//              w2b  [80][72]    @3200   5760
//              w3b  [80][72]    @8960   5760
//              h1h  [128][88]   @14720  11264
//              h2h  [128][88]   @25984  11264    (end 37248 halves = 74496 B)
// f32buf [128][72] floats @74496 B (36864 B)  => total 111360 B
__global__ void k_edgemlp(const float* __restrict__ eattr,
                          const float* __restrict__ we1, const float* __restrict__ be1,
                          const float* __restrict__ we2, const float* __restrict__ be2,
                          const float* __restrict__ we3, const float* __restrict__ be3,
                          int e) {
    extern __shared__ __half smh[];
    __half* es  = smh;
    __half* w1b = smh + 2048;
    __half* w2b = smh + 3200;
    __half* w3b = smh + 8960;
    __half* h1h = smh + 14720;
    __half* h2h = smh + 25984;
    float*  fb  = (float*)(smh + 37248);

    int tid = threadIdx.x;
    int pb = blockIdx.x * 128;

    for (int i = tid; i < 1152; i += 256) {
        int r = i / 72, c = i - r * 72;
        float v = 0.f;
        if (c < 64) v = (r < 8) ? __ldg(&we1[r * 64 + c]) : ((r == 8) ? __ldg(&be1[c]) : 0.f);
        w1b[i] = __float2half(v);
    }
    for (int i = tid; i < 5760; i += 256) {
        int r = i / 72, c = i - r * 72;
        float v2 = 0.f, v3 = 0.f;
        if (c < 64) {
            if (r < 64)      { v2 = __ldg(&we2[r * 64 + c]); v3 = __ldg(&we3[r * 64 + c]); }
            else if (r == 64){ v2 = __ldg(&be2[c]);          v3 = __ldg(&be3[c]); }
        }
        w2b[i] = __float2half(v2);
        w3b[i] = __float2half(v3);
    }
    for (int i = tid; i < 2048; i += 256) {
        int r = i >> 4, c = i & 15;
        float v = 0.f;
        if (c < 8) {
            int p = pb + r;
            if (p < e) v = __ldg(&eattr[g_eid[p] * 8 + c]);
        } else if (c == 8) v = 1.0f;
        es[i] = __float2half(v);
    }
    // bias/zero cols 64..87 of h1h/h2h (written once)
    for (int i = tid; i < 3072; i += 256) {
        int r = i / 24, c = 64 + (i - r * 24);
        __half v = __float2half((c == 64) ? 1.0f : 0.f);
        h1h[r * 88 + c] = v;
        h2h[r * 88 + c] = v;
    }
    __syncthreads();

    int w = tid >> 5;   // warp -> 16-row tile

    // ---- layer 1 (k=16: 8 attrs + bias) ----
    {
        HFragA a;
        wmma::load_matrix_sync(a, &es[w * 16 * 16], 16);
        #pragma unroll
        for (int nf = 0; nf < 4; nf++) {
            HFragC acc;
            wmma::fill_fragment(acc, 0.f);
            HFragB b;
            wmma::load_matrix_sync(b, &w1b[nf * 16], 72);
            wmma::mma_sync(acc, a, b, acc);
            wmma::store_matrix_sync(&fb[w * 16 * 72 + nf * 16], acc, 72, wmma::mem_row_major);
        }
    }
    __syncthreads();
    for (int i = tid; i < 8192; i += 256) {
        int r = i >> 6, c = i & 63;
        h1h[r * 88 + c] = __float2half(fmaxf(fb[r * 72 + c], 0.f));
    }
    __syncthreads();

    // ---- layer 2 (k=80) ----
    {
        HFragA a[5];
        #pragma unroll
        for (int k = 0; k < 5; k++)
            wmma::load_matrix_sync(a[k], &h1h[w * 16 * 88 + k * 16], 88);
        #pragma unroll
        for (int nf = 0; nf < 4; nf++) {
            HFragC acc;
            wmma::fill_fragment(acc, 0.f);
            #pragma unroll
            for (int k = 0; k < 5; k++) {
                HFragB b;
                wmma::load_matrix_sync(b, &w2b[k * 16 * 72 + nf * 16], 72);
                wmma::mma_sync(acc, a[k], b, acc);
            }
            wmma::store_matrix_sync(&fb[w * 16 * 72 + nf * 16], acc, 72, wmma::mem_row_major);
        }
    }
    __syncthreads();
    for (int i = tid; i < 8192; i += 256) {
        int r = i >> 6, c = i & 63;
        h2h[r * 88 + c] = __float2half(fmaxf(fb[r * 72 + c], 0.f));
    }
    __syncthreads();

    // ---- layer 3 (k=80) -> g_e (pre-relu; relu folded into k_attn) ----
    {
        HFragA a[5];
        #pragma unroll
        for (int k = 0; k < 5; k++)
            wmma::load_matrix_sync(a[k], &h2h[w * 16 * 88 + k * 16], 88);
        #pragma unroll
        for (int nf = 0; nf < 4; nf++) {
            HFragC acc;
            wmma::fill_fragment(acc, 0.f);
            #pragma unroll
            for (int k = 0; k < 5; k++) {
                HFragB b;
                wmma::load_matrix_sync(b, &w3b[k * 16 * 72 + nf * 16], 72);
                wmma::mma_sync(acc, a[k], b, acc);
            }
            wmma::store_matrix_sync(&g_e[(pb + w * 16) * 64 + nf * 16], acc, 64, wmma::mem_row_major);
        }
    }
}

// ---------------- attention: warp per node (relu applied to e loads) -------
__device__ __forceinline__ float dot4(float4 a, float4 b) {
    return a.x * b.x + a.y * b.y + a.z * b.z + a.w * b.w;
}
__device__ __forceinline__ float4 relu4(float4 a) {
    return make_float4(fmaxf(a.x, 0.f), fmaxf(a.y, 0.f), fmaxf(a.z, 0.f), fmaxf(a.w, 0.f));
}

__global__ void k_attn(int n) {
    int gw = (blockIdx.x * blockDim.x + threadIdx.x) >> 5;
    int lane = threadIdx.x & 31;
    if (gw >= n) return;
    int node = gw;
    int beg = g_rowptr[node], end = g_rowptr[node + 1];

    int h = lane >> 3;
    int c8 = (lane & 7) * 8;
    int chan = h * 64 + c8;

    float4 q0 = *(const float4*)&g_q[node * HC + chan];
    float4 q1 = *(const float4*)&g_q[node * HC + chan + 4];
    float4 gg0 = *(const float4*)&g_g[node * HC + chan];
    float4 gg1 = *(const float4*)&g_g[node * HC + chan + 4];
    float qb = g_qb[node * 4 + h];

    float s = 0.f;
    float4 av0 = {0,0,0,0}, av1 = {0,0,0,0};
    float4 at0 = {0,0,0,0}, at1 = {0,0,0,0};

    int p = beg;
    for (; p + 2 <= end; p += 2) {
        int srcA = g_src[p], srcB = g_src[p + 1];
        float4 kA0 = *(const float4*)&g_k[srcA * HC + chan];
        float4 kA1 = *(const float4*)&g_k[srcA * HC + chan + 4];
        float4 eA0 = relu4(*(const float4*)&g_e[p * 64 + c8]);
        float4 eA1 = relu4(*(const float4*)&g_e[p * 64 + c8 + 4]);
        float4 kB0 = *(const float4*)&g_k[srcB * HC + chan];
        float4 kB1 = *(const float4*)&g_k[srcB * HC + chan + 4];
        float4 eB0 = relu4(*(const float4*)&g_e[(p + 1) * 64 + c8]);
        float4 eB1 = relu4(*(const float4*)&g_e[(p + 1) * 64 + c8 + 4]);

        float dA = dot4(q0, kA0) + dot4(q1, kA1) + dot4(gg0, eA0) + dot4(gg1, eA1);
        float dB = dot4(q0, kB0) + dot4(q1, kB1) + dot4(gg0, eB0) + dot4(gg1, eB1);
        dA += __shfl_xor_sync(0xffffffffu, dA, 1);
        dB += __shfl_xor_sync(0xffffffffu, dB, 1);
        dA += __shfl_xor_sync(0xffffffffu, dA, 2);
        dB += __shfl_xor_sync(0xffffffffu, dB, 2);
        dA += __shfl_xor_sync(0xffffffffu, dA, 4);
        dB += __shfl_xor_sync(0xffffffffu, dB, 4);
        float peA = __expf((dA + qb) * 0.125f);
        float peB = __expf((dB + qb) * 0.125f);
        s += peA + peB;

        float4 vA0 = *(const float4*)&g_v[srcA * HC + chan];
        float4 vA1 = *(const float4*)&g_v[srcA * HC + chan + 4];
        float4 vB0 = *(const float4*)&g_v[srcB * HC + chan];
        float4 vB1 = *(const float4*)&g_v[srcB * HC + chan + 4];

        av0.x += peA * vA0.x + peB * vB0.x;  av0.y += peA * vA0.y + peB * vB0.y;
        av0.z += peA * vA0.z + peB * vB0.z;  av0.w += peA * vA0.w + peB * vB0.w;
        av1.x += peA * vA1.x + peB * vB1.x;  av1.y += peA * vA1.y + peB * vB1.y;
        av1.z += peA * vA1.z + peB * vB1.z;  av1.w += peA * vA1.w + peB * vB1.w;
        at0.x += peA * eA0.x + peB * eB0.x;  at0.y += peA * eA0.y + peB * eB0.y;
        at0.z += peA * eA0.z + peB * eB0.z;  at0.w += peA * eA0.w + peB * eB0.w;
        at1.x += peA * eA1.x + peB * eB1.x;  at1.y += peA * eA1.y + peB * eB1.y;
        at1.z += peA * eA1.z + peB * eB1.z;  at1.w += peA * eA1.w + peB * eB1.w;
    }
    if (p < end) {
        int src = g_src[p];
        float4 k0 = *(const float4*)&g_k[src * HC + chan];
        float4 k1 = *(const float4*)&g_k[src * HC + chan + 4];
        float4 e0 = relu4(*(const float4*)&g_e[p * 64 + c8]);
        float4 e1 = relu4(*(const float4*)&g_e[p * 64 + c8 + 4]);
        float d = dot4(q0, k0) + dot4(q1, k1) + dot4(gg0, e0) + dot4(gg1, e1);
        d += __shfl_xor_sync(0xffffffffu, d, 1);
        d += __shfl_xor_sync(0xffffffffu, d, 2);
        d += __shfl_xor_sync(0xffffffffu, d, 4);
        float pe = __expf((d + qb) * 0.125f);
        s += pe;
        float4 v0 = *(const float4*)&g_v[src * HC + chan];
        float4 v1 = *(const float4*)&g_v[src * HC + chan + 4];
        av0.x += pe * v0.x; av0.y += pe * v0.y; av0.z += pe * v0.z; av0.w += pe * v0.w;
        av1.x += pe * v1.x; av1.y += pe * v1.y; av1.z += pe * v1.z; av1.w += pe * v1.w;
        at0.x += pe * e0.x; at0.y += pe * e0.y; at0.z += pe * e0.z; at0.w += pe * e0.w;
        at1.x += pe * e1.x; at1.y += pe * e1.y; at1.z += pe * e1.z; at1.w += pe * e1.w;
    }

    float sinv = 1.f / (s + 1e-16f);
    float4 o0 = {av0.x * sinv, av0.y * sinv, av0.z * sinv, av0.w * sinv};
    float4 o1 = {av1.x * sinv, av1.y * sinv, av1.z * sinv, av1.w * sinv};
    float4 t0 = {at0.x * sinv, at0.y * sinv, at0.z * sinv, at0.w * sinv};
    float4 t1 = {at1.x * sinv, at1.y * sinv, at1.z * sinv, at1.w * sinv};
    *(float4*)&g_outv[node * HC + chan]     = o0;
    *(float4*)&g_outv[node * HC + chan + 4] = o1;
    *(float4*)&g_t   [node * HC + chan]     = t0;
    *(float4*)&g_t   [node * HC + chan + 4] = t1;
    if ((lane & 7) == 0) g_suma[node * 4 + h] = s * sinv;
}

// ---------------- epilogue 1 ----------------
__global__ void k_post(const float* __restrict__ wedge, const float* __restrict__ bedge,
                       const float* __restrict__ ln_g, const float* __restrict__ ln_b,
                       int n) {
    __shared__ float ts[16][HC];
    __shared__ float os[16][HC];
    int tid = threadIdx.x;
    int nb = blockIdx.x * 16;
    for (int i = tid; i < 16 * HC; i += 256) {
        int nn = nb + i / HC;
        ts[i / HC][i % HC] = (nn < n) ? g_t[nn * HC + (i % HC)] : 0.f;
    }
    __syncthreads();
    int h = tid >> 6;
    float acc[16];
    #pragma unroll
    for (int m = 0; m < 16; m++) acc[m] = 0.f;
    for (int i = 0; i < 64; i++) {
        float w = __ldg(&wedge[i * HC + tid]);
        #pragma unroll
        for (int m = 0; m < 16; m++) acc[m] += ts[m][h * 64 + i] * w;
    }
    float be = __ldg(&bedge[tid]);
    #pragma unroll
    for (int m = 0; m < 16; m++) {
        int nn = nb + m;
        if (nn < n) {
            float val = g_outv[nn * HC + tid] + g_suma[nn * 4 + h] * be
                      + g_skip[nn * HC + tid] + acc[m];
            os[m][tid] = val;
        }
    }
    __syncthreads();
    int wid = tid >> 5, lane = tid & 31;
    for (int m = wid; m < 16; m += 8) {
        int nn = nb + m;
        if (nn >= n) continue;
        float sum = 0.f, sq = 0.f;
        #pragma unroll
        for (int u = 0; u < 8; u++) {
            float v = os[m][u * 32 + lane];
            sum += v; sq += v * v;
        }
        #pragma unroll
        for (int off = 16; off; off >>= 1) {
            sum += __shfl_xor_sync(0xffffffffu, sum, off);
            sq  += __shfl_xor_sync(0xffffffffu, sq,  off);
        }
        float mu = sum * (1.f / 256.f);
        float var = sq * (1.f / 256.f) - mu * mu;
        float rs = rsqrtf(var + 1e-5f);
        #pragma unroll
        for (int u = 0; u < 8; u++) {
            int j = u * 32 + lane;
            float v = (os[m][j] - mu) * rs * __ldg(&ln_g[j]) + __ldg(&ln_b[j]);
            g_act[nn * HC + j] = fmaxf(v, 0.f);
        }
    }
}

// ---------------- epilogue 2 ----------------
__global__ void k_head(const float* __restrict__ w1, const float* __restrict__ b1,
                       const float* __restrict__ w2, const float* __restrict__ b2,
                       float* __restrict__ out, int n) {
    __shared__ float as[16][HC];
    __shared__ float hs[16][128];
    __shared__ float ls[16][NCLS];
    int tid = threadIdx.x;
    int nb = blockIdx.x * 16;
    for (int i = tid; i < 16 * HC; i += 128) {
        int nn = nb + i / HC;
        as[i / HC][i % HC] = (nn < n) ? g_act[nn * HC + (i % HC)] : 0.f;
    }
    __syncthreads();
    float acc[16];
    float bb = __ldg(&b1[tid]);
    #pragma unroll
    for (int m = 0; m < 16; m++) acc[m] = bb;
    for (int i = 0; i < HC; i++) {
        float w = __ldg(&w1[i * 128 + tid]);
        #pragma unroll
        for (int m = 0; m < 16; m++) acc[m] += as[m][i] * w;
    }
    #pragma unroll
    for (int m = 0; m < 16; m++) hs[m][tid] = fmaxf(acc[m], 0.f);
    __syncthreads();
    if (tid < 64) {
        int m = tid >> 2, c = tid & 3;
        float a = __ldg(&b2[c]);
        for (int i = 0; i < 128; i++) a += hs[m][i] * __ldg(&w2[i * NCLS + c]);
        ls[m][c] = a;
    }
    __syncthreads();
    if (tid < 16) {
        int nn = nb + tid;
        if (nn < n) {
            float l0 = ls[tid][0], l1 = ls[tid][1], l2 = ls[tid][2], l3 = ls[tid][3];
            float mx = fmaxf(fmaxf(l0, l1), fmaxf(l2, l3));
            float se = expf(l0 - mx) + expf(l1 - mx) + expf(l2 - mx) + expf(l3 - mx);
            float lse = mx + logf(se);
            out[nn * NCLS + 0] = l0 - lse;
            out[nn * NCLS + 1] = l1 - lse;
            out[nn * NCLS + 2] = l2 - lse;
            out[nn * NCLS + 3] = l3 - lse;
        }
    }
}

// ---------------- launcher ----------------
extern "C" void kernel_launch(void* const* d_in, const int* in_sizes, int n_in,
                              void* d_out, int out_size) {
    const float* x     = (const float*)d_in[0];
    const int*   ei    = (const int*)  d_in[1];
    const float* eattr = (const float*)d_in[2];
    const float* w00   = (const float*)d_in[3];
    const float* b00   = (const float*)d_in[4];
    const float* we1   = (const float*)d_in[5];
    const float* be1   = (const float*)d_in[6];
    const float* we2   = (const float*)d_in[7];
    const float* be2   = (const float*)d_in[8];
    const float* we3   = (const float*)d_in[9];
    const float* be3   = (const float*)d_in[10];
    const float* wq    = (const float*)d_in[11];
    const float* bq    = (const float*)d_in[12];
    const float* wk    = (const float*)d_in[13];
    const float* bk    = (const float*)d_in[14];
    const float* wv    = (const float*)d_in[15];
    const float* bv    = (const float*)d_in[16];
    const float* wedge = (const float*)d_in[17];
    const float* bedge = (const float*)d_in[18];
    const float* wskip = (const float*)d_in[19];
    const float* bskip = (const float*)d_in[20];
    const float* ln_g  = (const float*)d_in[21];
    const float* ln_b  = (const float*)d_in[22];
    const float* w1    = (const float*)d_in[23];
    const float* b1    = (const float*)d_in[24];
    const float* w2    = (const float*)d_in[25];
    const float* b2    = (const float*)d_in[26];
    float* out = (float*)d_out;

    int n = in_sizes[0] / NFEAT;
    int e = in_sizes[1] / 2;

    static const int EDGE_SMEM = 111360;   // bytes (see layout comment)
    static const int PROJ_SMEM = (5632 + 21120) * 2;   // 53504 bytes
    cudaFuncSetAttribute(k_edgemlp, cudaFuncAttributeMaxDynamicSharedMemorySize, EDGE_SMEM);
    cudaFuncSetAttribute(k_proj,    cudaFuncAttributeMaxDynamicSharedMemorySize, PROJ_SMEM);

    k_zero_deg<<<(n + 255) / 256, 256>>>(n);
    k_hist<<<(e + 255) / 256, 256>>>(ei, e);
    k_scan<<<1, 1024>>>(n);
    k_scatter<<<(e + 255) / 256, 256>>>(ei, e);

    k_node_embed<<<(n + 63) / 64, 256>>>(x, w00, b00, n);
    {
        dim3 grid((n + 63) / 64, 4);
        k_proj<<<grid, 256, PROJ_SMEM>>>(wq, bq, wk, bk, wv, bv, wskip, bskip, n);
    }
    k_g<<<(n + 31) / 32, 256>>>(wedge, bedge, n);

    k_edgemlp<<<(e + 127) / 128, 256, EDGE_SMEM>>>(eattr, we1, be1, we2, be2, we3, be3, e);

    k_attn<<<(n + 7) / 8, 256>>>(n);

    k_post<<<(n + 15) / 16, 256>>>(wedge, bedge, ln_g, ln_b, n);
    k_head<<<(n + 15) / 16, 128>>>(w1, b1, w2, b2, out, n);
}

// round 7
// speedup vs baseline: 1.4029x; 1.0679x over previous
#include <cuda_runtime.h>
#include <cuda_fp16.h>
#include <mma.h>
#include <math.h>

using namespace nvcuda;

#define NFEAT 16
#define EFEAT 8
#define HC    256
#define NCLS  4

static const int MAXN = 50000;
static const int NPAD = 50048;     // padded so 16-row wmma stores never overflow
static const int MAXE = 800000;

typedef wmma::fragment<wmma::matrix_a, 16, 16, 16, __half, wmma::row_major> HFragA;
typedef wmma::fragment<wmma::matrix_b, 16, 16, 16, __half, wmma::row_major> HFragB;
typedef wmma::fragment<wmma::accumulator, 16, 16, 16, float> HFragC;

// ---------------- scratch ----------------
__device__ float  g_x1  [MAXN * 64];
__device__ float  g_q   [NPAD * HC];
__device__ __half g_kh  [NPAD * HC];
__device__ __half g_vh  [NPAD * HC];
__device__ float  g_skip[NPAD * HC];
__device__ float  g_g   [MAXN * HC];
__device__ float  g_qb  [MAXN * 4];
__device__ __half g_eh  [MAXE * 64];   // edge MLP output, post-relu, dst-sorted
__device__ float  g_outv[MAXN * HC];
__device__ float  g_t   [MAXN * HC];
__device__ float  g_suma[MAXN * 4];
__device__ float  g_act [MAXN * HC];
__device__ int    g_deg [MAXN];
__device__ int    g_rowptr[MAXN + 1];
__device__ int    g_cursor[MAXN];
__device__ int    g_eid [MAXE];
__device__ int    g_src [MAXE];

// ---------------- CSR build ----------------
__global__ void k_zero_deg(int n) {
    int i = blockIdx.x * blockDim.x + threadIdx.x;
    if (i < n) g_deg[i] = 0;
}
__global__ void k_hist(const int* __restrict__ ei, int e) {
    int i = blockIdx.x * blockDim.x + threadIdx.x;
    if (i < e) atomicAdd(&g_deg[ei[e + i]], 1);
}
__global__ void k_scan(int n) {
    __shared__ int sh[1024];
    __shared__ int s_off;
    int tid = threadIdx.x;
    if (tid == 0) { s_off = 0; g_rowptr[0] = 0; }
    __syncthreads();
    for (int base = 0; base < n; base += 1024) {
        int i = base + tid;
        int val = (i < n) ? g_deg[i] : 0;
        sh[tid] = val;
        __syncthreads();
        for (int off = 1; off < 1024; off <<= 1) {
            int y = (tid >= off) ? sh[tid - off] : 0;
            __syncthreads();
            sh[tid] += y;
            __syncthreads();
        }
        int incl = sh[tid];
        if (i < n) {
            g_rowptr[i + 1] = s_off + incl;
            g_cursor[i]     = s_off + incl - val;
        }
        __syncthreads();
        if (tid == 0) s_off += sh[1023];
        __syncthreads();
    }
}
__global__ void k_scatter(const int* __restrict__ ei, int e) {
    int i = blockIdx.x * blockDim.x + threadIdx.x;
    if (i < e) {
        int dst = ei[e + i];
        int pos = atomicAdd(&g_cursor[dst], 1);
        g_eid[pos] = i;
        g_src[pos] = ei[i];
    }
}

// ---------------- node embed ----------------
__global__ void k_node_embed(const float* __restrict__ x,
                             const float* __restrict__ w00,
                             const float* __restrict__ b00, int n) {
    __shared__ float ws[NFEAT * 64];
    __shared__ float xs[64][NFEAT];
    int tid = threadIdx.x;
    for (int i = tid; i < NFEAT * 64; i += 256) ws[i] = w00[i];
    int nb = blockIdx.x * 64;
    for (int i = tid; i < 64 * NFEAT; i += 256) {
        int nn = nb + i / NFEAT;
        xs[i / NFEAT][i % NFEAT] = (nn < n) ? x[nn * NFEAT + (i % NFEAT)] : 0.f;
    }
    __syncthreads();
    int ln = tid >> 2;
    int node = nb + ln;
    int c0 = (tid & 3) * 16;
    if (node < n) {
        #pragma unroll
        for (int j = 0; j < 16; j++) {
            float acc = __ldg(&b00[c0 + j]);
            #pragma unroll
            for (int i = 0; i < NFEAT; i++) acc += xs[ln][i] * ws[i * 64 + c0 + j];
            g_x1[node * 64 + c0 + j] = fmaxf(acc, 0.f);
        }
    }
}

// ---------------- projections: fp16 wmma; k/v stored as fp16 --------------
__global__ void k_proj(const float* __restrict__ W0, const float* __restrict__ B0,
                       const float* __restrict__ W1, const float* __restrict__ B1,
                       const float* __restrict__ W2, const float* __restrict__ B2,
                       const float* __restrict__ W3, const float* __restrict__ B3,
                       int n) {
    int sel = blockIdx.y;
    const float* W = (sel == 0) ? W0 : (sel == 1) ? W1 : (sel == 2) ? W2 : W3;
    const float* B = (sel == 0) ? B0 : (sel == 1) ? B1 : (sel == 2) ? B2 : B3;
    bool half_out = (sel == 1 || sel == 2);
    float*  outf = (sel == 0) ? g_q : g_skip;
    __half* outh = (sel == 1) ? g_kh : g_vh;

    extern __shared__ __half smh[];
    __half* xsh = smh;            // [64][88]
    __half* wsh = smh + 5632;     // [80][264]
    __shared__ float fbp[8][256]; // per-warp 16x16 f32 bounce buffer

    int tid = threadIdx.x;
    int nb = blockIdx.x * 64;

    for (int i = tid; i < 64 * 88; i += 256) {
        int r = i / 88, c = i - r * 88;
        float v = 0.f;
        if (c < 64) {
            int node = nb + r;
            if (node < n) v = __ldg(&g_x1[node * 64 + c]);
        } else if (c == 64) v = 1.0f;
        xsh[i] = __float2half(v);
    }
    for (int i = tid; i < 80 * 264; i += 256) {
        int r = i / 264, c = i - r * 264;
        float v = 0.f;
        if (c < 256) {
            if (r < 64) v = __ldg(&W[r * 256 + c]);
            else if (r == 64) v = __ldg(&B[c]);
        }
        wsh[i] = __float2half(v);
    }
    __syncthreads();

    int w = tid >> 5, lane = tid & 31;
    int rt = w >> 1;        // 4 row tiles of 16
    int ch = w & 1;         // 128-col half

    HFragA a[5];
    #pragma unroll
    for (int k = 0; k < 5; k++)
        wmma::load_matrix_sync(a[k], &xsh[rt * 16 * 88 + k * 16], 88);

    #pragma unroll
    for (int nf = 0; nf < 8; nf++) {
        int c0 = ch * 128 + nf * 16;
        HFragC acc;
        wmma::fill_fragment(acc, 0.f);
        #pragma unroll
        for (int k = 0; k < 5; k++) {
            HFragB b;
            wmma::load_matrix_sync(b, &wsh[k * 16 * 264 + c0], 264);
            wmma::mma_sync(acc, a[k], b, acc);
        }
        if (!half_out) {
            wmma::store_matrix_sync(&outf[(nb + rt * 16) * HC + c0], acc, HC, wmma::mem_row_major);
        } else {
            wmma::store_matrix_sync(&fbp[w][0], acc, 16, wmma::mem_row_major);
            __syncwarp();
            int r = lane >> 1, cf = (lane & 1) * 8;
            const float* src = &fbp[w][r * 16 + cf];
            __half hb[8];
            #pragma unroll
            for (int j = 0; j < 8; j++) hb[j] = __float2half(src[j]);
            *(uint4*)&outh[(nb + rt * 16 + r) * HC + c0 + cf] = *(uint4*)hb;
            __syncwarp();
        }
    }
}

// ---------------- g = per-head wedge^T @ q ; qb = q . bedge ----------------
__global__ void k_g(const float* __restrict__ wedge, const float* __restrict__ bedge,
                    int n) {
    __shared__ float qs[32 * HC];
    int tid = threadIdx.x;
    int nb = blockIdx.x * 32;
    for (int i = tid; i < 2048; i += 256) {
        int row = i >> 6, q4 = i & 63;
        int node = nb + row;
        float4 v = make_float4(0.f, 0.f, 0.f, 0.f);
        if (node < n) v = *(const float4*)&g_q[node * HC + q4 * 4];
        *(float4*)&qs[row * HC + q4 * 4] = v;
    }
    __syncthreads();
    int h = tid >> 6, ii = tid & 63;
    float acc[32];
    #pragma unroll
    for (int m = 0; m < 32; m++) acc[m] = 0.f;
    for (int c = 0; c < 64; c++) {
        float w = __ldg(&wedge[ii * HC + h * 64 + c]);
        #pragma unroll
        for (int m = 0; m < 32; m++) acc[m] += qs[m * HC + h * 64 + c] * w;
    }
    #pragma unroll
    for (int m = 0; m < 32; m++) {
        int nn = nb + m;
        if (nn < n) g_g[nn * HC + tid] = acc[m];
    }
    if (tid < 128) {
        int m = tid >> 2, h2 = tid & 3;
        int nn = nb + m;
        if (nn < n) {
            float s = 0.f;
            for (int c = 0; c < 64; c++) s += qs[m * HC + h2 * 64 + c] * __ldg(&bedge[h2 * 64 + c]);
            g_qb[nn * 4 + h2] = s;
        }
    }
}

// ---------------- edge MLP: fp16 wmma, 128 edges/block; fp16 relu'd out ----
__global__ void k_edgemlp(const float* __restrict__ eattr,
                          const float* __restrict__ we1, const float* __restrict__ be1,
                          const float* __restrict__ we2, const float* __restrict__ be2,
                          const float* __restrict__ we3, const float* __restrict__ be3,
                          int e) {
    extern __shared__ __half smh[];
    __half* es  = smh;           // [128][16]
    __half* w1b = smh + 2048;    // [16][72]
    __half* w2b = smh + 3200;    // [80][72]
    __half* w3b = smh + 8960;    // [80][72]
    __half* h1h = smh + 14720;   // [128][88]
    __half* h2h = smh + 25984;   // [128][88]
    float*  fb  = (float*)(smh + 37248);   // [128][72] f32

    int tid = threadIdx.x;
    int pb = blockIdx.x * 128;

    for (int i = tid; i < 1152; i += 256) {
        int r = i / 72, c = i - r * 72;
        float v = 0.f;
        if (c < 64) v = (r < 8) ? __ldg(&we1[r * 64 + c]) : ((r == 8) ? __ldg(&be1[c]) : 0.f);
        w1b[i] = __float2half(v);
    }
    for (int i = tid; i < 5760; i += 256) {
        int r = i / 72, c = i - r * 72;
        float v2 = 0.f, v3 = 0.f;
        if (c < 64) {
            if (r < 64)      { v2 = __ldg(&we2[r * 64 + c]); v3 = __ldg(&we3[r * 64 + c]); }
            else if (r == 64){ v2 = __ldg(&be2[c]);          v3 = __ldg(&be3[c]); }
        }
        w2b[i] = __float2half(v2);
        w3b[i] = __float2half(v3);
    }
    for (int i = tid; i < 2048; i += 256) {
        int r = i >> 4, c = i & 15;
        float v = 0.f;
        if (c < 8) {
            int p = pb + r;
            if (p < e) v = __ldg(&eattr[g_eid[p] * 8 + c]);
        } else if (c == 8) v = 1.0f;
        es[i] = __float2half(v);
    }
    for (int i = tid; i < 3072; i += 256) {
        int r = i / 24, c = 64 + (i - r * 24);
        __half v = __float2half((c == 64) ? 1.0f : 0.f);
        h1h[r * 88 + c] = v;
        h2h[r * 88 + c] = v;
    }
    __syncthreads();

    int w = tid >> 5;

    // ---- layer 1 (k=16) ----
    {
        HFragA a;
        wmma::load_matrix_sync(a, &es[w * 16 * 16], 16);
        #pragma unroll
        for (int nf = 0; nf < 4; nf++) {
            HFragC acc;
            wmma::fill_fragment(acc, 0.f);
            HFragB b;
            wmma::load_matrix_sync(b, &w1b[nf * 16], 72);
            wmma::mma_sync(acc, a, b, acc);
            wmma::store_matrix_sync(&fb[w * 16 * 72 + nf * 16], acc, 72, wmma::mem_row_major);
        }
    }
    __syncthreads();
    for (int i = tid; i < 8192; i += 256) {
        int r = i >> 6, c = i & 63;
        h1h[r * 88 + c] = __float2half(fmaxf(fb[r * 72 + c], 0.f));
    }
    __syncthreads();

    // ---- layer 2 (k=80) ----
    {
        HFragA a[5];
        #pragma unroll
        for (int k = 0; k < 5; k++)
            wmma::load_matrix_sync(a[k], &h1h[w * 16 * 88 + k * 16], 88);
        #pragma unroll
        for (int nf = 0; nf < 4; nf++) {
            HFragC acc;
            wmma::fill_fragment(acc, 0.f);
            #pragma unroll
            for (int k = 0; k < 5; k++) {
                HFragB b;
                wmma::load_matrix_sync(b, &w2b[k * 16 * 72 + nf * 16], 72);
                wmma::mma_sync(acc, a[k], b, acc);
            }
            wmma::store_matrix_sync(&fb[w * 16 * 72 + nf * 16], acc, 72, wmma::mem_row_major);
        }
    }
    __syncthreads();
    for (int i = tid; i < 8192; i += 256) {
        int r = i >> 6, c = i & 63;
        h2h[r * 88 + c] = __float2half(fmaxf(fb[r * 72 + c], 0.f));
    }
    __syncthreads();

    // ---- layer 3 (k=80) -> fb -> relu -> fp16 g_eh ----
    {
        HFragA a[5];
        #pragma unroll
        for (int k = 0; k < 5; k++)
            wmma::load_matrix_sync(a[k], &h2h[w * 16 * 88 + k * 16], 88);
        #pragma unroll
        for (int nf = 0; nf < 4; nf++) {
            HFragC acc;
            wmma::fill_fragment(acc, 0.f);
            #pragma unroll
            for (int k = 0; k < 5; k++) {
                HFragB b;
                wmma::load_matrix_sync(b, &w3b[k * 16 * 72 + nf * 16], 72);
                wmma::mma_sync(acc, a[k], b, acc);
            }
            wmma::store_matrix_sync(&fb[w * 16 * 72 + nf * 16], acc, 72, wmma::mem_row_major);
        }
    }
    __syncthreads();
    {
        int nrows = min(128, e - pb);
        for (int i = tid * 2; i < nrows * 64; i += 512) {
            int r = i >> 6, c = i & 63;
            __half2 hv = __floats2half2_rn(fmaxf(fb[r * 72 + c], 0.f),
                                           fmaxf(fb[r * 72 + c + 1], 0.f));
            *(__half2*)&g_eh[(pb + r) * 64 + c] = hv;
        }
    }
}

// ---------------- attention: warp per node, fp16 k/v/e ---------------------
__device__ __forceinline__ float dot4(float4 a, float4 b) {
    return a.x * b.x + a.y * b.y + a.z * b.z + a.w * b.w;
}
__device__ __forceinline__ void ldh8(const __half* p, float4& a, float4& b) {
    uint4 u = *(const uint4*)p;
    float2 f0 = __half22float2(*(__half2*)&u.x);
    float2 f1 = __half22float2(*(__half2*)&u.y);
    float2 f2 = __half22float2(*(__half2*)&u.z);
    float2 f3 = __half22float2(*(__half2*)&u.w);
    a = make_float4(f0.x, f0.y, f1.x, f1.y);
    b = make_float4(f2.x, f2.y, f3.x, f3.y);
}

__global__ void k_attn(int n) {
    int gw = (blockIdx.x * blockDim.x + threadIdx.x) >> 5;
    int lane = threadIdx.x & 31;
    if (gw >= n) return;
    int node = gw;
    int beg = g_rowptr[node], end = g_rowptr[node + 1];

    int h = lane >> 3;
    int c8 = (lane & 7) * 8;
    int chan = h * 64 + c8;

    float4 q0 = *(const float4*)&g_q[node * HC + chan];
    float4 q1 = *(const float4*)&g_q[node * HC + chan + 4];
    float4 gg0 = *(const float4*)&g_g[node * HC + chan];
    float4 gg1 = *(const float4*)&g_g[node * HC + chan + 4];
    float qb = g_qb[node * 4 + h];

    float s = 0.f;
    float4 av0 = {0,0,0,0}, av1 = {0,0,0,0};
    float4 at0 = {0,0,0,0}, at1 = {0,0,0,0};

    int p = beg;
    for (; p + 2 <= end; p += 2) {
        int srcA = g_src[p], srcB = g_src[p + 1];
        float4 kA0, kA1, kB0, kB1, eA0, eA1, eB0, eB1;
        ldh8(&g_kh[srcA * HC + chan], kA0, kA1);
        ldh8(&g_eh[p * 64 + c8],      eA0, eA1);
        ldh8(&g_kh[srcB * HC + chan], kB0, kB1);
        ldh8(&g_eh[(p + 1) * 64 + c8],eB0, eB1);

        float dA = dot4(q0, kA0) + dot4(q1, kA1) + dot4(gg0, eA0) + dot4(gg1, eA1);
        float dB = dot4(q0, kB0) + dot4(q1, kB1) + dot4(gg0, eB0) + dot4(gg1, eB1);
        dA += __shfl_xor_sync(0xffffffffu, dA, 1);
        dB += __shfl_xor_sync(0xffffffffu, dB, 1);
        dA += __shfl_xor_sync(0xffffffffu, dA, 2);
        dB += __shfl_xor_sync(0xffffffffu, dB, 2);
        dA += __shfl_xor_sync(0xffffffffu, dA, 4);
        dB += __shfl_xor_sync(0xffffffffu, dB, 4);
        float peA = __expf((dA + qb) * 0.125f);
        float peB = __expf((dB + qb) * 0.125f);
        s += peA + peB;

        float4 vA0, vA1, vB0, vB1;
        ldh8(&g_vh[srcA * HC + chan], vA0, vA1);
        ldh8(&g_vh[srcB * HC + chan], vB0, vB1);

        av0.x += peA * vA0.x + peB * vB0.x;  av0.y += peA * vA0.y + peB * vB0.y;
        av0.z += peA * vA0.z + peB * vB0.z;  av0.w += peA * vA0.w + peB * vB0.w;
        av1.x += peA * vA1.x + peB * vB1.x;  av1.y += peA * vA1.y + peB * vB1.y;
        av1.z += peA * vA1.z + peB * vB1.z;  av1.w += peA * vA1.w + peB * vB1.w;
        at0.x += peA * eA0.x + peB * eB0.x;  at0.y += peA * eA0.y + peB * eB0.y;
        at0.z += peA * eA0.z + peB * eB0.z;  at0.w += peA * eA0.w + peB * eB0.w;
        at1.x += peA * eA1.x + peB * eB1.x;  at1.y += peA * eA1.y + peB * eB1.y;
        at1.z += peA * eA1.z + peB * eB1.z;  at1.w += peA * eA1.w + peB * eB1.w;
    }
    if (p < end) {
        int src = g_src[p];
        float4 k0, k1, e0, e1;
        ldh8(&g_kh[src * HC + chan], k0, k1);
        ldh8(&g_eh[p * 64 + c8],     e0, e1);
        float d = dot4(q0, k0) + dot4(q1, k1) + dot4(gg0, e0) + dot4(gg1, e1);
        d += __shfl_xor_sync(0xffffffffu, d, 1);
        d += __shfl_xor_sync(0xffffffffu, d, 2);
        d += __shfl_xor_sync(0xffffffffu, d, 4);
        float pe = __expf((d + qb) * 0.125f);
        s += pe;
        float4 v0, v1;
        ldh8(&g_vh[src * HC + chan], v0, v1);
        av0.x += pe * v0.x; av0.y += pe * v0.y; av0.z += pe * v0.z; av0.w += pe * v0.w;
        av1.x += pe * v1.x; av1.y += pe * v1.y; av1.z += pe * v1.z; av1.w += pe * v1.w;
        at0.x += pe * e0.x; at0.y += pe * e0.y; at0.z += pe * e0.z; at0.w += pe * e0.w;
        at1.x += pe * e1.x; at1.y += pe * e1.y; at1.z += pe * e1.z; at1.w += pe * e1.w;
    }

    float sinv = 1.f / (s + 1e-16f);
    float4 o0 = {av0.x * sinv, av0.y * sinv, av0.z * sinv, av0.w * sinv};
    float4 o1 = {av1.x * sinv, av1.y * sinv, av1.z * sinv, av1.w * sinv};
    float4 t0 = {at0.x * sinv, at0.y * sinv, at0.z * sinv, at0.w * sinv};
    float4 t1 = {at1.x * sinv, at1.y * sinv, at1.z * sinv, at1.w * sinv};
    *(float4*)&g_outv[node * HC + chan]     = o0;
    *(float4*)&g_outv[node * HC + chan + 4] = o1;
    *(float4*)&g_t   [node * HC + chan]     = t0;
    *(float4*)&g_t   [node * HC + chan + 4] = t1;
    if ((lane & 7) == 0) g_suma[node * 4 + h] = s * sinv;
}

// ---------------- epilogue 1 ----------------
__global__ void k_post(const float* __restrict__ wedge, const float* __restrict__ bedge,
                       const float* __restrict__ ln_g, const float* __restrict__ ln_b,
                       int n) {
    __shared__ float ts[16][HC];
    __shared__ float os[16][HC];
    int tid = threadIdx.x;
    int nb = blockIdx.x * 16;
    for (int i = tid; i < 16 * HC; i += 256) {
        int nn = nb + i / HC;
        ts[i / HC][i % HC] = (nn < n) ? g_t[nn * HC + (i % HC)] : 0.f;
    }
    __syncthreads();
    int h = tid >> 6;
    float acc[16];
    #pragma unroll
    for (int m = 0; m < 16; m++) acc[m] = 0.f;
    for (int i = 0; i < 64; i++) {
        float w = __ldg(&wedge[i * HC + tid]);
        #pragma unroll
        for (int m = 0; m < 16; m++) acc[m] += ts[m][h * 64 + i] * w;
    }
    float be = __ldg(&bedge[tid]);
    #pragma unroll
    for (int m = 0; m < 16; m++) {
        int nn = nb + m;
        if (nn < n) {
            float val = g_outv[nn * HC + tid] + g_suma[nn * 4 + h] * be
                      + g_skip[nn * HC + tid] + acc[m];
            os[m][tid] = val;
        }
    }
    __syncthreads();
    int wid = tid >> 5, lane = tid & 31;
    for (int m = wid; m < 16; m += 8) {
        int nn = nb + m;
        if (nn >= n) continue;
        float sum = 0.f, sq = 0.f;
        #pragma unroll
        for (int u = 0; u < 8; u++) {
            float v = os[m][u * 32 + lane];
            sum += v; sq += v * v;
        }
        #pragma unroll
        for (int off = 16; off; off >>= 1) {
            sum += __shfl_xor_sync(0xffffffffu, sum, off);
            sq  += __shfl_xor_sync(0xffffffffu, sq,  off);
        }
        float mu = sum * (1.f / 256.f);
        float var = sq * (1.f / 256.f) - mu * mu;
        float rs = rsqrtf(var + 1e-5f);
        #pragma unroll
        for (int u = 0; u < 8; u++) {
            int j = u * 32 + lane;
            float v = (os[m][j] - mu) * rs * __ldg(&ln_g[j]) + __ldg(&ln_b[j]);
            g_act[nn * HC + j] = fmaxf(v, 0.f);
        }
    }
}

// ---------------- epilogue 2 ----------------
__global__ void k_head(const float* __restrict__ w1, const float* __restrict__ b1,
                       const float* __restrict__ w2, const float* __restrict__ b2,
                       float* __restrict__ out, int n) {
    __shared__ float as[16][HC];
    __shared__ float hs[16][128];
    __shared__ float ls[16][NCLS];
    int tid = threadIdx.x;
    int nb = blockIdx.x * 16;
    for (int i = tid; i < 16 * HC; i += 128) {
        int nn = nb + i / HC;
        as[i / HC][i % HC] = (nn < n) ? g_act[nn * HC + (i % HC)] : 0.f;
    }
    __syncthreads();
    float acc[16];
    float bb = __ldg(&b1[tid]);
    #pragma unroll
    for (int m = 0; m < 16; m++) acc[m] = bb;
    for (int i = 0; i < HC; i++) {
        float w = __ldg(&w1[i * 128 + tid]);
        #pragma unroll
        for (int m = 0; m < 16; m++) acc[m] += as[m][i] * w;
    }
    #pragma unroll
    for (int m = 0; m < 16; m++) hs[m][tid] = fmaxf(acc[m], 0.f);
    __syncthreads();
    if (tid < 64) {
        int m = tid >> 2, c = tid & 3;
        float a = __ldg(&b2[c]);
        for (int i = 0; i < 128; i++) a += hs[m][i] * __ldg(&w2[i * NCLS + c]);
        ls[m][c] = a;
    }
    __syncthreads();
    if (tid < 16) {
        int nn = nb + tid;
        if (nn < n) {
            float l0 = ls[tid][0], l1 = ls[tid][1], l2 = ls[tid][2], l3 = ls[tid][3];
            float mx = fmaxf(fmaxf(l0, l1), fmaxf(l2, l3));
            float se = expf(l0 - mx) + expf(l1 - mx) + expf(l2 - mx) + expf(l3 - mx);
            float lse = mx + logf(se);
            out[nn * NCLS + 0] = l0 - lse;
            out[nn * NCLS + 1] = l1 - lse;
            out[nn * NCLS + 2] = l2 - lse;
            out[nn * NCLS + 3] = l3 - lse;
        }
    }
}

// ---------------- launcher ----------------
extern "C" void kernel_launch(void* const* d_in, const int* in_sizes, int n_in,
                              void* d_out, int out_size) {
    const float* x     = (const float*)d_in[0];
    const int*   ei    = (const int*)  d_in[1];
    const float* eattr = (const float*)d_in[2];
    const float* w00   = (const float*)d_in[3];
    const float* b00   = (const float*)d_in[4];
    const float* we1   = (const float*)d_in[5];
    const float* be1   = (const float*)d_in[6];
    const float* we2   = (const float*)d_in[7];
    const float* be2   = (const float*)d_in[8];
    const float* we3   = (const float*)d_in[9];
    const float* be3   = (const float*)d_in[10];
    const float* wq    = (const float*)d_in[11];
    const float* bq    = (const float*)d_in[12];
    const float* wk    = (const float*)d_in[13];
    const float* bk    = (const float*)d_in[14];
    const float* wv    = (const float*)d_in[15];
    const float* bv    = (const float*)d_in[16];
    const float* wedge = (const float*)d_in[17];
    const float* bedge = (const float*)d_in[18];
    const float* wskip = (const float*)d_in[19];
    const float* bskip = (const float*)d_in[20];
    const float* ln_g  = (const float*)d_in[21];
    const float* ln_b  = (const float*)d_in[22];
    const float* w1    = (const float*)d_in[23];
    const float* b1    = (const float*)d_in[24];
    const float* w2    = (const float*)d_in[25];
    const float* b2    = (const float*)d_in[26];
    float* out = (float*)d_out;

    int n = in_sizes[0] / NFEAT;
    int e = in_sizes[1] / 2;

    static const int EDGE_SMEM = 111360;
    static const int PROJ_SMEM = (5632 + 21120) * 2;   // 53504 bytes dynamic
    cudaFuncSetAttribute(k_edgemlp, cudaFuncAttributeMaxDynamicSharedMemorySize, EDGE_SMEM);
    cudaFuncSetAttribute(k_proj,    cudaFuncAttributeMaxDynamicSharedMemorySize, PROJ_SMEM);

    k_zero_deg<<<(n + 255) / 256, 256>>>(n);
    k_hist<<<(e + 255) / 256, 256>>>(ei, e);
    k_scan<<<1, 1024>>>(n);
    k_scatter<<<(e + 255) / 256, 256>>>(ei, e);

    k_node_embed<<<(n + 63) / 64, 256>>>(x, w00, b00, n);
    {
        dim3 grid((n + 63) / 64, 4);
        k_proj<<<grid, 256, PROJ_SMEM>>>(wq, bq, wk, bk, wv, bv, wskip, bskip, n);
    }
    k_g<<<(n + 31) / 32, 256>>>(wedge, bedge, n);

    k_edgemlp<<<(e + 127) / 128, 256, EDGE_SMEM>>>(eattr, we1, be1, we2, be2, we3, be3, e);

    k_attn<<<(n + 7) / 8, 256>>>(n);

    k_post<<<(n + 15) / 16, 256>>>(wedge, bedge, ln_g, ln_b, n);
    k_head<<<(n + 15) / 16, 128>>>(w1, b1, w2, b2, out, n);
}

// round 8
// speedup vs baseline: 1.4915x; 1.0632x over previous
#include <cuda_runtime.h>
#include <cuda_fp16.h>
#include <mma.h>
#include <math.h>

using namespace nvcuda;

#define NFEAT 16
#define EFEAT 8
#define HC    256
#define NCLS  4

static const int MAXN = 50000;
static const int NPAD = 50048;
static const int MAXE = 800000;

typedef wmma::fragment<wmma::matrix_a, 16, 16, 16, __half, wmma::row_major> HFragA;
typedef wmma::fragment<wmma::matrix_b, 16, 16, 16, __half, wmma::row_major> HFragB;
typedef wmma::fragment<wmma::accumulator, 16, 16, 16, float> HFragC;

// ---------------- scratch ----------------
__device__ float  g_x1  [MAXN * 64];
__device__ float  g_q   [NPAD * HC];
__device__ __half g_kh  [NPAD * HC];
__device__ __half g_vh  [NPAD * HC];
__device__ float  g_skip[NPAD * HC];
__device__ float  g_g   [MAXN * HC];
__device__ float  g_qb  [MAXN * 4];
__device__ __half g_eh  [MAXE * 64];
__device__ float  g_outv[MAXN * HC];
__device__ float  g_t   [MAXN * HC];
__device__ float  g_suma[MAXN * 4];
__device__ float  g_act [MAXN * HC];
__device__ float  g_wtt [HC * 64];     // wedge transposed: wtt[(h*64+c)*64 + ii]
__device__ int    g_deg [MAXN];
__device__ int    g_rowptr[MAXN + 1];
__device__ int    g_cursor[MAXN];
__device__ int    g_eid [MAXE];
__device__ int    g_src [MAXE];

// ---------------- CSR build ----------------
__global__ void k_zero_deg(int n) {
    int i = blockIdx.x * blockDim.x + threadIdx.x;
    if (i < n) g_deg[i] = 0;
}
__global__ void k_hist(const int* __restrict__ ei, int e) {
    int i = blockIdx.x * blockDim.x + threadIdx.x;
    if (i < e) atomicAdd(&g_deg[ei[e + i]], 1);
}
__global__ void k_scan(int n) {
    __shared__ int sh[1024];
    __shared__ int s_off;
    int tid = threadIdx.x;
    if (tid == 0) { s_off = 0; g_rowptr[0] = 0; }
    __syncthreads();
    for (int base = 0; base < n; base += 1024) {
        int i = base + tid;
        int val = (i < n) ? g_deg[i] : 0;
        sh[tid] = val;
        __syncthreads();
        for (int off = 1; off < 1024; off <<= 1) {
            int y = (tid >= off) ? sh[tid - off] : 0;
            __syncthreads();
            sh[tid] += y;
            __syncthreads();
        }
        int incl = sh[tid];
        if (i < n) {
            g_rowptr[i + 1] = s_off + incl;
            g_cursor[i]     = s_off + incl - val;
        }
        __syncthreads();
        if (tid == 0) s_off += sh[1023];
        __syncthreads();
    }
}
__global__ void k_scatter(const int* __restrict__ ei, int e) {
    int i = blockIdx.x * blockDim.x + threadIdx.x;
    if (i < e) {
        int dst = ei[e + i];
        int pos = atomicAdd(&g_cursor[dst], 1);
        g_eid[pos] = i;
        g_src[pos] = ei[i];
    }
}

// ---------------- wedge transpose (one-time, tiny) ----------------
__global__ void k_wtt(const float* __restrict__ wedge) {
    int idx = blockIdx.x * 256 + threadIdx.x;   // 64 blocks
    int cg = idx >> 6, ii = idx & 63;
    g_wtt[cg * 64 + ii] = wedge[ii * HC + cg];
}

// ---------------- node embed ----------------
__global__ void k_node_embed(const float* __restrict__ x,
                             const float* __restrict__ w00,
                             const float* __restrict__ b00, int n) {
    __shared__ float ws[NFEAT * 64];
    __shared__ float xs[64][NFEAT];
    int tid = threadIdx.x;
    for (int i = tid; i < NFEAT * 64; i += 256) ws[i] = w00[i];
    int nb = blockIdx.x * 64;
    for (int i = tid; i < 64 * NFEAT; i += 256) {
        int nn = nb + i / NFEAT;
        xs[i / NFEAT][i % NFEAT] = (nn < n) ? x[nn * NFEAT + (i % NFEAT)] : 0.f;
    }
    __syncthreads();
    int ln = tid >> 2;
    int node = nb + ln;
    int c0 = (tid & 3) * 16;
    if (node < n) {
        #pragma unroll
        for (int j = 0; j < 16; j++) {
            float acc = __ldg(&b00[c0 + j]);
            #pragma unroll
            for (int i = 0; i < NFEAT; i++) acc += xs[ln][i] * ws[i * 64 + c0 + j];
            g_x1[node * 64 + c0 + j] = fmaxf(acc, 0.f);
        }
    }
}

// ---------------- projections: fp16 wmma; k/v stored as fp16 --------------
__global__ void k_proj(const float* __restrict__ W0, const float* __restrict__ B0,
                       const float* __restrict__ W1, const float* __restrict__ B1,
                       const float* __restrict__ W2, const float* __restrict__ B2,
                       const float* __restrict__ W3, const float* __restrict__ B3,
                       int n) {
    int sel = blockIdx.y;
    const float* W = (sel == 0) ? W0 : (sel == 1) ? W1 : (sel == 2) ? W2 : W3;
    const float* B = (sel == 0) ? B0 : (sel == 1) ? B1 : (sel == 2) ? B2 : B3;
    bool half_out = (sel == 1 || sel == 2);
    float*  outf = (sel == 0) ? g_q : g_skip;
    __half* outh = (sel == 1) ? g_kh : g_vh;

    extern __shared__ __half smh[];
    __half* xsh = smh;            // [64][88]
    __half* wsh = smh + 5632;     // [80][264]
    __shared__ float fbp[8][256];

    int tid = threadIdx.x;
    int nb = blockIdx.x * 64;

    for (int i = tid; i < 64 * 88; i += 256) {
        int r = i / 88, c = i - r * 88;
        float v = 0.f;
        if (c < 64) {
            int node = nb + r;
            if (node < n) v = __ldg(&g_x1[node * 64 + c]);
        } else if (c == 64) v = 1.0f;
        xsh[i] = __float2half(v);
    }
    for (int i = tid; i < 80 * 264; i += 256) {
        int r = i / 264, c = i - r * 264;
        float v = 0.f;
        if (c < 256) {
            if (r < 64) v = __ldg(&W[r * 256 + c]);
            else if (r == 64) v = __ldg(&B[c]);
        }
        wsh[i] = __float2half(v);
    }
    __syncthreads();

    int w = tid >> 5, lane = tid & 31;
    int rt = w >> 1;
    int ch = w & 1;

    HFragA a[5];
    #pragma unroll
    for (int k = 0; k < 5; k++)
        wmma::load_matrix_sync(a[k], &xsh[rt * 16 * 88 + k * 16], 88);

    #pragma unroll
    for (int nf = 0; nf < 8; nf++) {
        int c0 = ch * 128 + nf * 16;
        HFragC acc;
        wmma::fill_fragment(acc, 0.f);
        #pragma unroll
        for (int k = 0; k < 5; k++) {
            HFragB b;
            wmma::load_matrix_sync(b, &wsh[k * 16 * 264 + c0], 264);
            wmma::mma_sync(acc, a[k], b, acc);
        }
        if (!half_out) {
            wmma::store_matrix_sync(&outf[(nb + rt * 16) * HC + c0], acc, HC, wmma::mem_row_major);
        } else {
            wmma::store_matrix_sync(&fbp[w][0], acc, 16, wmma::mem_row_major);
            __syncwarp();
            int r = lane >> 1, cf = (lane & 1) * 8;
            const float* src = &fbp[w][r * 16 + cf];
            __half hb[8];
            #pragma unroll
            for (int j = 0; j < 8; j++) hb[j] = __float2half(src[j]);
            *(uint4*)&outh[(nb + rt * 16 + r) * HC + c0 + cf] = *(uint4*)hb;
            __syncwarp();
        }
    }
}

// ---------------- g = per-head wedge^T @ q (coalesced via g_wtt) -----------
__global__ void k_g(const float* __restrict__ bedge, int n) {
    __shared__ float qs[32 * HC];
    int tid = threadIdx.x;
    int nb = blockIdx.x * 32;
    for (int i = tid; i < 2048; i += 256) {
        int row = i >> 6, q4 = i & 63;
        int node = nb + row;
        float4 v = make_float4(0.f, 0.f, 0.f, 0.f);
        if (node < n) v = *(const float4*)&g_q[node * HC + q4 * 4];
        *(float4*)&qs[row * HC + q4 * 4] = v;
    }
    __syncthreads();
    int h = tid >> 6, ii = tid & 63;
    float acc[32];
    #pragma unroll
    for (int m = 0; m < 32; m++) acc[m] = 0.f;
    for (int c = 0; c < 64; c++) {
        float w = __ldg(&g_wtt[(h * 64 + c) * 64 + ii]);   // coalesced
        #pragma unroll
        for (int m = 0; m < 32; m++) acc[m] += qs[m * HC + h * 64 + c] * w;
    }
    #pragma unroll
    for (int m = 0; m < 32; m++) {
        int nn = nb + m;
        if (nn < n) g_g[nn * HC + tid] = acc[m];
    }
    if (tid < 128) {
        int m = tid >> 2, h2 = tid & 3;
        int nn = nb + m;
        if (nn < n) {
            float s = 0.f;
            for (int c = 0; c < 64; c++) s += qs[m * HC + h2 * 64 + c] * __ldg(&bedge[h2 * 64 + c]);
            g_qb[nn * 4 + h2] = s;
        }
    }
}

// ---------------- edge MLP: fp16 wmma, 128 edges/block; fp16 relu'd out ----
__global__ void k_edgemlp(const float* __restrict__ eattr,
                          const float* __restrict__ we1, const float* __restrict__ be1,
                          const float* __restrict__ we2, const float* __restrict__ be2,
                          const float* __restrict__ we3, const float* __restrict__ be3,
                          int e) {
    extern __shared__ __half smh[];
    __half* es  = smh;
    __half* w1b = smh + 2048;
    __half* w2b = smh + 3200;
    __half* w3b = smh + 8960;
    __half* h1h = smh + 14720;
    __half* h2h = smh + 25984;
    float*  fb  = (float*)(smh + 37248);

    int tid = threadIdx.x;
    int pb = blockIdx.x * 128;

    for (int i = tid; i < 1152; i += 256) {
        int r = i / 72, c = i - r * 72;
        float v = 0.f;
        if (c < 64) v = (r < 8) ? __ldg(&we1[r * 64 + c]) : ((r == 8) ? __ldg(&be1[c]) : 0.f);
        w1b[i] = __float2half(v);
    }
    for (int i = tid; i < 5760; i += 256) {
        int r = i / 72, c = i - r * 72;
        float v2 = 0.f, v3 = 0.f;
        if (c < 64) {
            if (r < 64)      { v2 = __ldg(&we2[r * 64 + c]); v3 = __ldg(&we3[r * 64 + c]); }
            else if (r == 64){ v2 = __ldg(&be2[c]);          v3 = __ldg(&be3[c]); }
        }
        w2b[i] = __float2half(v2);
        w3b[i] = __float2half(v3);
    }
    for (int i = tid; i < 2048; i += 256) {
        int r = i >> 4, c = i & 15;
        float v = 0.f;
        if (c < 8) {
            int p = pb + r;
            if (p < e) v = __ldg(&eattr[g_eid[p] * 8 + c]);
        } else if (c == 8) v = 1.0f;
        es[i] = __float2half(v);
    }
    for (int i = tid; i < 3072; i += 256) {
        int r = i / 24, c = 64 + (i - r * 24);
        __half v = __float2half((c == 64) ? 1.0f : 0.f);
        h1h[r * 88 + c] = v;
        h2h[r * 88 + c] = v;
    }
    __syncthreads();

    int w = tid >> 5;

    // ---- layer 1 (k=16) ----
    {
        HFragA a;
        wmma::load_matrix_sync(a, &es[w * 16 * 16], 16);
        #pragma unroll
        for (int nf = 0; nf < 4; nf++) {
            HFragC acc;
            wmma::fill_fragment(acc, 0.f);
            HFragB b;
            wmma::load_matrix_sync(b, &w1b[nf * 16], 72);
            wmma::mma_sync(acc, a, b, acc);
            wmma::store_matrix_sync(&fb[w * 16 * 72 + nf * 16], acc, 72, wmma::mem_row_major);
        }
    }
    __syncthreads();
    for (int i = tid; i < 8192; i += 256) {
        int r = i >> 6, c = i & 63;
        h1h[r * 88 + c] = __float2half(fmaxf(fb[r * 72 + c], 0.f));
    }
    __syncthreads();

    // ---- layer 2 (k=80) ----
    {
        HFragA a[5];
        #pragma unroll
        for (int k = 0; k < 5; k++)
            wmma::load_matrix_sync(a[k], &h1h[w * 16 * 88 + k * 16], 88);
        #pragma unroll
        for (int nf = 0; nf < 4; nf++) {
            HFragC acc;
            wmma::fill_fragment(acc, 0.f);
            #pragma unroll
            for (int k = 0; k < 5; k++) {
                HFragB b;
                wmma::load_matrix_sync(b, &w2b[k * 16 * 72 + nf * 16], 72);
                wmma::mma_sync(acc, a[k], b, acc);
            }
            wmma::store_matrix_sync(&fb[w * 16 * 72 + nf * 16], acc, 72, wmma::mem_row_major);
        }
    }
    __syncthreads();
    for (int i = tid; i < 8192; i += 256) {
        int r = i >> 6, c = i & 63;
        h2h[r * 88 + c] = __float2half(fmaxf(fb[r * 72 + c], 0.f));
    }
    __syncthreads();

    // ---- layer 3 (k=80) -> relu -> fp16 g_eh ----
    {
        HFragA a[5];
        #pragma unroll
        for (int k = 0; k < 5; k++)
            wmma::load_matrix_sync(a[k], &h2h[w * 16 * 88 + k * 16], 88);
        #pragma unroll
        for (int nf = 0; nf < 4; nf++) {
            HFragC acc;
            wmma::fill_fragment(acc, 0.f);
            #pragma unroll
            for (int k = 0; k < 5; k++) {
                HFragB b;
                wmma::load_matrix_sync(b, &w3b[k * 16 * 72 + nf * 16], 72);
                wmma::mma_sync(acc, a[k], b, acc);
            }
            wmma::store_matrix_sync(&fb[w * 16 * 72 + nf * 16], acc, 72, wmma::mem_row_major);
        }
    }
    __syncthreads();
    {
        int nrows = min(128, e - pb);
        for (int i = tid * 2; i < nrows * 64; i += 512) {
            int r = i >> 6, c = i & 63;
            __half2 hv = __floats2half2_rn(fmaxf(fb[r * 72 + c], 0.f),
                                           fmaxf(fb[r * 72 + c + 1], 0.f));
            *(__half2*)&g_eh[(pb + r) * 64 + c] = hv;
        }
    }
}

// ---------------- attention: warp per node, 4-edge unroll ------------------
__device__ __forceinline__ float dot4(float4 a, float4 b) {
    return a.x * b.x + a.y * b.y + a.z * b.z + a.w * b.w;
}
__device__ __forceinline__ void ldh8(const __half* p, float4& a, float4& b) {
    uint4 u = *(const uint4*)p;
    float2 f0 = __half22float2(*(__half2*)&u.x);
    float2 f1 = __half22float2(*(__half2*)&u.y);
    float2 f2 = __half22float2(*(__half2*)&u.z);
    float2 f3 = __half22float2(*(__half2*)&u.w);
    a = make_float4(f0.x, f0.y, f1.x, f1.y);
    b = make_float4(f2.x, f2.y, f3.x, f3.y);
}

__global__ void __launch_bounds__(256, 4) k_attn(int n) {
    int gw = (blockIdx.x * blockDim.x + threadIdx.x) >> 5;
    int lane = threadIdx.x & 31;
    if (gw >= n) return;
    int node = gw;
    int beg = g_rowptr[node], end = g_rowptr[node + 1];

    int h = lane >> 3;
    int c8 = (lane & 7) * 8;
    int chan = h * 64 + c8;

    float4 q0 = *(const float4*)&g_q[node * HC + chan];
    float4 q1 = *(const float4*)&g_q[node * HC + chan + 4];
    float4 gg0 = *(const float4*)&g_g[node * HC + chan];
    float4 gg1 = *(const float4*)&g_g[node * HC + chan + 4];
    float qb = g_qb[node * 4 + h];

    float s = 0.f;
    float4 av0 = {0,0,0,0}, av1 = {0,0,0,0};
    float4 at0 = {0,0,0,0}, at1 = {0,0,0,0};

    int p = beg;
    for (; p + 4 <= end; p += 4) {
        int src[4];
        #pragma unroll
        for (int u = 0; u < 4; u++) src[u] = g_src[p + u];

        float d[4];
        float4 e0[4], e1[4];
        #pragma unroll
        for (int u = 0; u < 4; u++) {
            float4 k0, k1;
            ldh8(&g_kh[src[u] * HC + chan], k0, k1);
            ldh8(&g_eh[(p + u) * 64 + c8], e0[u], e1[u]);
            d[u] = dot4(q0, k0) + dot4(q1, k1) + dot4(gg0, e0[u]) + dot4(gg1, e1[u]);
        }
        #pragma unroll
        for (int off = 1; off < 8; off <<= 1) {
            #pragma unroll
            for (int u = 0; u < 4; u++)
                d[u] += __shfl_xor_sync(0xffffffffu, d[u], off);
        }
        float pe[4];
        #pragma unroll
        for (int u = 0; u < 4; u++) {
            pe[u] = __expf((d[u] + qb) * 0.125f);
            s += pe[u];
        }
        #pragma unroll
        for (int u = 0; u < 4; u++) {
            float4 v0, v1;
            ldh8(&g_vh[src[u] * HC + chan], v0, v1);
            av0.x += pe[u] * v0.x;  av0.y += pe[u] * v0.y;
            av0.z += pe[u] * v0.z;  av0.w += pe[u] * v0.w;
            av1.x += pe[u] * v1.x;  av1.y += pe[u] * v1.y;
            av1.z += pe[u] * v1.z;  av1.w += pe[u] * v1.w;
            at0.x += pe[u] * e0[u].x;  at0.y += pe[u] * e0[u].y;
            at0.z += pe[u] * e0[u].z;  at0.w += pe[u] * e0[u].w;
            at1.x += pe[u] * e1[u].x;  at1.y += pe[u] * e1[u].y;
            at1.z += pe[u] * e1[u].z;  at1.w += pe[u] * e1[u].w;
        }
    }
    for (; p < end; p++) {
        int src = g_src[p];
        float4 k0, k1, e0, e1;
        ldh8(&g_kh[src * HC + chan], k0, k1);
        ldh8(&g_eh[p * 64 + c8],     e0, e1);
        float d = dot4(q0, k0) + dot4(q1, k1) + dot4(gg0, e0) + dot4(gg1, e1);
        d += __shfl_xor_sync(0xffffffffu, d, 1);
        d += __shfl_xor_sync(0xffffffffu, d, 2);
        d += __shfl_xor_sync(0xffffffffu, d, 4);
        float pe = __expf((d + qb) * 0.125f);
        s += pe;
        float4 v0, v1;
        ldh8(&g_vh[src * HC + chan], v0, v1);
        av0.x += pe * v0.x; av0.y += pe * v0.y; av0.z += pe * v0.z; av0.w += pe * v0.w;
        av1.x += pe * v1.x; av1.y += pe * v1.y; av1.z += pe * v1.z; av1.w += pe * v1.w;
        at0.x += pe * e0.x; at0.y += pe * e0.y; at0.z += pe * e0.z; at0.w += pe * e0.w;
        at1.x += pe * e1.x; at1.y += pe * e1.y; at1.z += pe * e1.z; at1.w += pe * e1.w;
    }

    float sinv = 1.f / (s + 1e-16f);
    float4 o0 = {av0.x * sinv, av0.y * sinv, av0.z * sinv, av0.w * sinv};
    float4 o1 = {av1.x * sinv, av1.y * sinv, av1.z * sinv, av1.w * sinv};
    float4 t0 = {at0.x * sinv, at0.y * sinv, at0.z * sinv, at0.w * sinv};
    float4 t1 = {at1.x * sinv, at1.y * sinv, at1.z * sinv, at1.w * sinv};
    *(float4*)&g_outv[node * HC + chan]     = o0;
    *(float4*)&g_outv[node * HC + chan + 4] = o1;
    *(float4*)&g_t   [node * HC + chan]     = t0;
    *(float4*)&g_t   [node * HC + chan + 4] = t1;
    if ((lane & 7) == 0) g_suma[node * 4 + h] = s * sinv;
}

// ---------------- epilogue 1 ----------------
__global__ void k_post(const float* __restrict__ wedge, const float* __restrict__ bedge,
                       const float* __restrict__ ln_g, const float* __restrict__ ln_b,
                       int n) {
    __shared__ float ts[16][HC];
    __shared__ float os[16][HC];
    int tid = threadIdx.x;
    int nb = blockIdx.x * 16;
    for (int i = tid; i < 16 * HC; i += 256) {
        int nn = nb + i / HC;
        ts[i / HC][i % HC] = (nn < n) ? g_t[nn * HC + (i % HC)] : 0.f;
    }
    __syncthreads();
    int h = tid >> 6;
    float acc[16];
    #pragma unroll
    for (int m = 0; m < 16; m++) acc[m] = 0.f;
    for (int i = 0; i < 64; i++) {
        float w = __ldg(&wedge[i * HC + tid]);
        #pragma unroll
        for (int m = 0; m < 16; m++) acc[m] += ts[m][h * 64 + i] * w;
    }
    float be = __ldg(&bedge[tid]);
    #pragma unroll
    for (int m = 0; m < 16; m++) {
        int nn = nb + m;
        if (nn < n) {
            float val = g_outv[nn * HC + tid] + g_suma[nn * 4 + h] * be
                      + g_skip[nn * HC + tid] + acc[m];
            os[m][tid] = val;
        }
    }
    __syncthreads();
    int wid = tid >> 5, lane = tid & 31;
    for (int m = wid; m < 16; m += 8) {
        int nn = nb + m;
        if (nn >= n) continue;
        float sum = 0.f, sq = 0.f;
        #pragma unroll
        for (int u = 0; u < 8; u++) {
            float v = os[m][u * 32 + lane];
            sum += v; sq += v * v;
        }
        #pragma unroll
        for (int off = 16; off; off >>= 1) {
            sum += __shfl_xor_sync(0xffffffffu, sum, off);
            sq  += __shfl_xor_sync(0xffffffffu, sq,  off);
        }
        float mu = sum * (1.f / 256.f);
        float var = sq * (1.f / 256.f) - mu * mu;
        float rs = rsqrtf(var + 1e-5f);
        #pragma unroll
        for (int u = 0; u < 8; u++) {
            int j = u * 32 + lane;
            float v = (os[m][j] - mu) * rs * __ldg(&ln_g[j]) + __ldg(&ln_b[j]);
            g_act[nn * HC + j] = fmaxf(v, 0.f);
        }
    }
}

// ---------------- epilogue 2 ----------------
__global__ void k_head(const float* __restrict__ w1, const float* __restrict__ b1,
                       const float* __restrict__ w2, const float* __restrict__ b2,
                       float* __restrict__ out, int n) {
    __shared__ float as[16][HC];
    __shared__ float hs[16][128];
    __shared__ float ls[16][NCLS];
    int tid = threadIdx.x;
    int nb = blockIdx.x * 16;
    for (int i = tid; i < 16 * HC; i += 128) {
        int nn = nb + i / HC;
        as[i / HC][i % HC] = (nn < n) ? g_act[nn * HC + (i % HC)] : 0.f;
    }
    __syncthreads();
    float acc[16];
    float bb = __ldg(&b1[tid]);
    #pragma unroll
    for (int m = 0; m < 16; m++) acc[m] = bb;
    for (int i = 0; i < HC; i++) {
        float w = __ldg(&w1[i * 128 + tid]);
        #pragma unroll
        for (int m = 0; m < 16; m++) acc[m] += as[m][i] * w;
    }
    #pragma unroll
    for (int m = 0; m < 16; m++) hs[m][tid] = fmaxf(acc[m], 0.f);
    __syncthreads();
    if (tid < 64) {
        int m = tid >> 2, c = tid & 3;
        float a = __ldg(&b2[c]);
        for (int i = 0; i < 128; i++) a += hs[m][i] * __ldg(&w2[i * NCLS + c]);
        ls[m][c] = a;
    }
    __syncthreads();
    if (tid < 16) {
        int nn = nb + tid;
        if (nn < n) {
            float l0 = ls[tid][0], l1 = ls[tid][1], l2 = ls[tid][2], l3 = ls[tid][3];
            float mx = fmaxf(fmaxf(l0, l1), fmaxf(l2, l3));
            float se = expf(l0 - mx) + expf(l1 - mx) + expf(l2 - mx) + expf(l3 - mx);
            float lse = mx + logf(se);
            out[nn * NCLS + 0] = l0 - lse;
            out[nn * NCLS + 1] = l1 - lse;
            out[nn * NCLS + 2] = l2 - lse;
            out[nn * NCLS + 3] = l3 - lse;
        }
    }
}

// ---------------- launcher ----------------
extern "C" void kernel_launch(void* const* d_in, const int* in_sizes, int n_in,
                              void* d_out, int out_size) {
    const float* x     = (const float*)d_in[0];
    const int*   ei    = (const int*)  d_in[1];
    const float* eattr = (const float*)d_in[2];
    const float* w00   = (const float*)d_in[3];
    const float* b00   = (const float*)d_in[4];
    const float* we1   = (const float*)d_in[5];
    const float* be1   = (const float*)d_in[6];
    const float* we2   = (const float*)d_in[7];
    const float* be2   = (const float*)d_in[8];
    const float* we3   = (const float*)d_in[9];
    const float* be3   = (const float*)d_in[10];
    const float* wq    = (const float*)d_in[11];
    const float* bq    = (const float*)d_in[12];
    const float* wk    = (const float*)d_in[13];
    const float* bk    = (const float*)d_in[14];
    const float* wv    = (const float*)d_in[15];
    const float* bv    = (const float*)d_in[16];
    const float* wedge = (const float*)d_in[17];
    const float* bedge = (const float*)d_in[18];
    const float* wskip = (const float*)d_in[19];
    const float* bskip = (const float*)d_in[20];
    const float* ln_g  = (const float*)d_in[21];
    const float* ln_b  = (const float*)d_in[22];
    const float* w1    = (const float*)d_in[23];
    const float* b1    = (const float*)d_in[24];
    const float* w2    = (const float*)d_in[25];
    const float* b2    = (const float*)d_in[26];
    float* out = (float*)d_out;

    int n = in_sizes[0] / NFEAT;
    int e = in_sizes[1] / 2;

    static const int EDGE_SMEM = 111360;
    static const int PROJ_SMEM = (5632 + 21120) * 2;
    cudaFuncSetAttribute(k_edgemlp, cudaFuncAttributeMaxDynamicSharedMemorySize, EDGE_SMEM);
    cudaFuncSetAttribute(k_proj,    cudaFuncAttributeMaxDynamicSharedMemorySize, PROJ_SMEM);

    k_zero_deg<<<(n + 255) / 256, 256>>>(n);
    k_hist<<<(e + 255) / 256, 256>>>(ei, e);
    k_scan<<<1, 1024>>>(n);
    k_scatter<<<(e + 255) / 256, 256>>>(ei, e);
    k_wtt<<<64, 256>>>(wedge);

    k_node_embed<<<(n + 63) / 64, 256>>>(x, w00, b00, n);
    {
        dim3 grid((n + 63) / 64, 4);
        k_proj<<<grid, 256, PROJ_SMEM>>>(wq, bq, wk, bk, wv, bv, wskip, bskip, n);
    }
    k_g<<<(n + 31) / 32, 256>>>(bedge, n);

    k_edgemlp<<<(e + 127) / 128, 256, EDGE_SMEM>>>(eattr, we1, be1, we2, be2, we3, be3, e);

    k_attn<<<(n + 7) / 8, 256>>>(n);

    k_post<<<(n + 15) / 16, 256>>>(wedge, bedge, ln_g, ln_b, n);
    k_head<<<(n + 15) / 16, 128>>>(w1, b1, w2, b2, out, n);
}

// round 9
// speedup vs baseline: 1.5554x; 1.0428x over previous
#include <cuda_runtime.h>
#include <cuda_fp16.h>
#include <mma.h>
#include <math.h>

using namespace nvcuda;

#define NFEAT 16
#define EFEAT 8
#define HC    256
#define NCLS  4

static const int MAXN = 50000;
static const int NPAD = 50048;
static const int MAXE = 800000;

typedef wmma::fragment<wmma::matrix_a, 16, 16, 16, __half, wmma::row_major> HFragA;
typedef wmma::fragment<wmma::matrix_b, 16, 16, 16, __half, wmma::row_major> HFragB;
typedef wmma::fragment<wmma::accumulator, 16, 16, 16, float> HFragC;

// ---------------- scratch ----------------
__device__ float  g_x1  [MAXN * 64];
__device__ float  g_q   [NPAD * HC];
__device__ __half g_kh  [NPAD * HC];
__device__ __half g_vh  [NPAD * HC];
__device__ float  g_skip[NPAD * HC];
__device__ float  g_g   [MAXN * HC];
__device__ float  g_qb  [MAXN * 4];
__device__ __half g_eh  [MAXE * 64];
__device__ float  g_outv[MAXN * HC];
__device__ float  g_t   [MAXN * HC];
__device__ float  g_suma[MAXN * 4];
__device__ float  g_wtt [HC * 64];
__device__ int    g_deg [MAXN];
__device__ int    g_rowptr[MAXN + 1];
__device__ int    g_cursor[MAXN];
__device__ int    g_eid [MAXE];
__device__ int    g_src [MAXE];

// ---------------- CSR build ----------------
__global__ void k_zero_deg(int n) {
    int i = blockIdx.x * blockDim.x + threadIdx.x;
    if (i < n) g_deg[i] = 0;
}
__global__ void k_hist(const int* __restrict__ ei, int e) {
    int i = blockIdx.x * blockDim.x + threadIdx.x;
    if (i < e) atomicAdd(&g_deg[ei[e + i]], 1);
}
__global__ void k_scan(int n) {
    __shared__ int sh[1024];
    __shared__ int s_off;
    int tid = threadIdx.x;
    if (tid == 0) { s_off = 0; g_rowptr[0] = 0; }
    __syncthreads();
    for (int base = 0; base < n; base += 1024) {
        int i = base + tid;
        int val = (i < n) ? g_deg[i] : 0;
        sh[tid] = val;
        __syncthreads();
        for (int off = 1; off < 1024; off <<= 1) {
            int y = (tid >= off) ? sh[tid - off] : 0;
            __syncthreads();
            sh[tid] += y;
            __syncthreads();
        }
        int incl = sh[tid];
        if (i < n) {
            g_rowptr[i + 1] = s_off + incl;
            g_cursor[i]     = s_off + incl - val;
        }
        __syncthreads();
        if (tid == 0) s_off += sh[1023];
        __syncthreads();
    }
}
__global__ void k_scatter(const int* __restrict__ ei, int e) {
    int i = blockIdx.x * blockDim.x + threadIdx.x;
    if (i < e) {
        int dst = ei[e + i];
        int pos = atomicAdd(&g_cursor[dst], 1);
        g_eid[pos] = i;
        g_src[pos] = ei[i];
    }
}

// ---------------- wedge transpose (one-time, tiny) ----------------
__global__ void k_wtt(const float* __restrict__ wedge) {
    int idx = blockIdx.x * 256 + threadIdx.x;
    int cg = idx >> 6, ii = idx & 63;
    g_wtt[cg * 64 + ii] = wedge[ii * HC + cg];
}

// ---------------- node embed ----------------
__global__ void k_node_embed(const float* __restrict__ x,
                             const float* __restrict__ w00,
                             const float* __restrict__ b00, int n) {
    __shared__ float ws[NFEAT * 64];
    __shared__ float xs[64][NFEAT];
    int tid = threadIdx.x;
    for (int i = tid; i < NFEAT * 64; i += 256) ws[i] = w00[i];
    int nb = blockIdx.x * 64;
    for (int i = tid; i < 64 * NFEAT; i += 256) {
        int nn = nb + i / NFEAT;
        xs[i / NFEAT][i % NFEAT] = (nn < n) ? x[nn * NFEAT + (i % NFEAT)] : 0.f;
    }
    __syncthreads();
    int ln = tid >> 2;
    int node = nb + ln;
    int c0 = (tid & 3) * 16;
    if (node < n) {
        #pragma unroll
        for (int j = 0; j < 16; j++) {
            float acc = __ldg(&b00[c0 + j]);
            #pragma unroll
            for (int i = 0; i < NFEAT; i++) acc += xs[ln][i] * ws[i * 64 + c0 + j];
            g_x1[node * 64 + c0 + j] = fmaxf(acc, 0.f);
        }
    }
}

// ---------------- projections: fp16 wmma; k/v stored as fp16 --------------
__global__ void k_proj(const float* __restrict__ W0, const float* __restrict__ B0,
                       const float* __restrict__ W1, const float* __restrict__ B1,
                       const float* __restrict__ W2, const float* __restrict__ B2,
                       const float* __restrict__ W3, const float* __restrict__ B3,
                       int n) {
    int sel = blockIdx.y;
    const float* W = (sel == 0) ? W0 : (sel == 1) ? W1 : (sel == 2) ? W2 : W3;
    const float* B = (sel == 0) ? B0 : (sel == 1) ? B1 : (sel == 2) ? B2 : B3;
    bool half_out = (sel == 1 || sel == 2);
    float*  outf = (sel == 0) ? g_q : g_skip;
    __half* outh = (sel == 1) ? g_kh : g_vh;

    extern __shared__ __half smh[];
    __half* xsh = smh;            // [64][88]
    __half* wsh = smh + 5632;     // [80][264]
    __shared__ float fbp[8][256];

    int tid = threadIdx.x;
    int nb = blockIdx.x * 64;

    for (int i = tid; i < 64 * 88; i += 256) {
        int r = i / 88, c = i - r * 88;
        float v = 0.f;
        if (c < 64) {
            int node = nb + r;
            if (node < n) v = __ldg(&g_x1[node * 64 + c]);
        } else if (c == 64) v = 1.0f;
        xsh[i] = __float2half(v);
    }
    for (int i = tid; i < 80 * 264; i += 256) {
        int r = i / 264, c = i - r * 264;
        float v = 0.f;
        if (c < 256) {
            if (r < 64) v = __ldg(&W[r * 256 + c]);
            else if (r == 64) v = __ldg(&B[c]);
        }
        wsh[i] = __float2half(v);
    }
    __syncthreads();

    int w = tid >> 5, lane = tid & 31;
    int rt = w >> 1;
    int ch = w & 1;

    HFragA a[5];
    #pragma unroll
    for (int k = 0; k < 5; k++)
        wmma::load_matrix_sync(a[k], &xsh[rt * 16 * 88 + k * 16], 88);

    #pragma unroll
    for (int nf = 0; nf < 8; nf++) {
        int c0 = ch * 128 + nf * 16;
        HFragC acc;
        wmma::fill_fragment(acc, 0.f);
        #pragma unroll
        for (int k = 0; k < 5; k++) {
            HFragB b;
            wmma::load_matrix_sync(b, &wsh[k * 16 * 264 + c0], 264);
            wmma::mma_sync(acc, a[k], b, acc);
        }
        if (!half_out) {
            wmma::store_matrix_sync(&outf[(nb + rt * 16) * HC + c0], acc, HC, wmma::mem_row_major);
        } else {
            wmma::store_matrix_sync(&fbp[w][0], acc, 16, wmma::mem_row_major);
            __syncwarp();
            int r = lane >> 1, cf = (lane & 1) * 8;
            const float* src = &fbp[w][r * 16 + cf];
            __half hb[8];
            #pragma unroll
            for (int j = 0; j < 8; j++) hb[j] = __float2half(src[j]);
            *(uint4*)&outh[(nb + rt * 16 + r) * HC + c0 + cf] = *(uint4*)hb;
            __syncwarp();
        }
    }
}

// ---------------- g = per-head wedge^T @ q (coalesced via g_wtt) -----------
__global__ void k_g(const float* __restrict__ bedge, int n) {
    __shared__ float qs[32 * HC];
    int tid = threadIdx.x;
    int nb = blockIdx.x * 32;
    for (int i = tid; i < 2048; i += 256) {
        int row = i >> 6, q4 = i & 63;
        int node = nb + row;
        float4 v = make_float4(0.f, 0.f, 0.f, 0.f);
        if (node < n) v = *(const float4*)&g_q[node * HC + q4 * 4];
        *(float4*)&qs[row * HC + q4 * 4] = v;
    }
    __syncthreads();
    int h = tid >> 6, ii = tid & 63;
    float acc[32];
    #pragma unroll
    for (int m = 0; m < 32; m++) acc[m] = 0.f;
    for (int c = 0; c < 64; c++) {
        float w = __ldg(&g_wtt[(h * 64 + c) * 64 + ii]);
        #pragma unroll
        for (int m = 0; m < 32; m++) acc[m] += qs[m * HC + h * 64 + c] * w;
    }
    #pragma unroll
    for (int m = 0; m < 32; m++) {
        int nn = nb + m;
        if (nn < n) g_g[nn * HC + tid] = acc[m];
    }
    if (tid < 128) {
        int m = tid >> 2, h2 = tid & 3;
        int nn = nb + m;
        if (nn < n) {
            float s = 0.f;
            for (int c = 0; c < 64; c++) s += qs[m * HC + h2 * 64 + c] * __ldg(&bedge[h2 * 64 + c]);
            g_qb[nn * 4 + h2] = s;
        }
    }
}

// ---------------- edge MLP: fp16 wmma, 128 edges/block ---------------------
__global__ void k_edgemlp(const float* __restrict__ eattr,
                          const float* __restrict__ we1, const float* __restrict__ be1,
                          const float* __restrict__ we2, const float* __restrict__ be2,
                          const float* __restrict__ we3, const float* __restrict__ be3,
                          int e) {
    extern __shared__ __half smh[];
    __half* es  = smh;
    __half* w1b = smh + 2048;
    __half* w2b = smh + 3200;
    __half* w3b = smh + 8960;
    __half* h1h = smh + 14720;
    __half* h2h = smh + 25984;
    float*  fb  = (float*)(smh + 37248);

    int tid = threadIdx.x;
    int pb = blockIdx.x * 128;

    for (int i = tid; i < 1152; i += 256) {
        int r = i / 72, c = i - r * 72;
        float v = 0.f;
        if (c < 64) v = (r < 8) ? __ldg(&we1[r * 64 + c]) : ((r == 8) ? __ldg(&be1[c]) : 0.f);
        w1b[i] = __float2half(v);
    }
    for (int i = tid; i < 5760; i += 256) {
        int r = i / 72, c = i - r * 72;
        float v2 = 0.f, v3 = 0.f;
        if (c < 64) {
            if (r < 64)      { v2 = __ldg(&we2[r * 64 + c]); v3 = __ldg(&we3[r * 64 + c]); }
            else if (r == 64){ v2 = __ldg(&be2[c]);          v3 = __ldg(&be3[c]); }
        }
        w2b[i] = __float2half(v2);
        w3b[i] = __float2half(v3);
    }
    for (int i = tid; i < 2048; i += 256) {
        int r = i >> 4, c = i & 15;
        float v = 0.f;
        if (c < 8) {
            int p = pb + r;
            if (p < e) v = __ldg(&eattr[g_eid[p] * 8 + c]);
        } else if (c == 8) v = 1.0f;
        es[i] = __float2half(v);
    }
    for (int i = tid; i < 3072; i += 256) {
        int r = i / 24, c = 64 + (i - r * 24);
        __half v = __float2half((c == 64) ? 1.0f : 0.f);
        h1h[r * 88 + c] = v;
        h2h[r * 88 + c] = v;
    }
    __syncthreads();

    int w = tid >> 5;

    // ---- layer 1 (k=16) ----
    {
        HFragA a;
        wmma::load_matrix_sync(a, &es[w * 16 * 16], 16);
        #pragma unroll
        for (int nf = 0; nf < 4; nf++) {
            HFragC acc;
            wmma::fill_fragment(acc, 0.f);
            HFragB b;
            wmma::load_matrix_sync(b, &w1b[nf * 16], 72);
            wmma::mma_sync(acc, a, b, acc);
            wmma::store_matrix_sync(&fb[w * 16 * 72 + nf * 16], acc, 72, wmma::mem_row_major);
        }
    }
    __syncthreads();
    for (int i = tid; i < 8192; i += 256) {
        int r = i >> 6, c = i & 63;
        h1h[r * 88 + c] = __float2half(fmaxf(fb[r * 72 + c], 0.f));
    }
    __syncthreads();

    // ---- layer 2 (k=80) ----
    {
        HFragA a[5];
        #pragma unroll
        for (int k = 0; k < 5; k++)
            wmma::load_matrix_sync(a[k], &h1h[w * 16 * 88 + k * 16], 88);
        #pragma unroll
        for (int nf = 0; nf < 4; nf++) {
            HFragC acc;
            wmma::fill_fragment(acc, 0.f);
            #pragma unroll
            for (int k = 0; k < 5; k++) {
                HFragB b;
                wmma::load_matrix_sync(b, &w2b[k * 16 * 72 + nf * 16], 72);
                wmma::mma_sync(acc, a[k], b, acc);
            }
            wmma::store_matrix_sync(&fb[w * 16 * 72 + nf * 16], acc, 72, wmma::mem_row_major);
        }
    }
    __syncthreads();
    for (int i = tid; i < 8192; i += 256) {
        int r = i >> 6, c = i & 63;
        h2h[r * 88 + c] = __float2half(fmaxf(fb[r * 72 + c], 0.f));
    }
    __syncthreads();

    // ---- layer 3 (k=80) -> relu -> fp16 g_eh ----
    {
        HFragA a[5];
        #pragma unroll
        for (int k = 0; k < 5; k++)
            wmma::load_matrix_sync(a[k], &h2h[w * 16 * 88 + k * 16], 88);
        #pragma unroll
        for (int nf = 0; nf < 4; nf++) {
            HFragC acc;
            wmma::fill_fragment(acc, 0.f);
            #pragma unroll
            for (int k = 0; k < 5; k++) {
                HFragB b;
                wmma::load_matrix_sync(b, &w3b[k * 16 * 72 + nf * 16], 72);
                wmma::mma_sync(acc, a[k], b, acc);
            }
            wmma::store_matrix_sync(&fb[w * 16 * 72 + nf * 16], acc, 72, wmma::mem_row_major);
        }
    }
    __syncthreads();
    {
        int nrows = min(128, e - pb);
        for (int i = tid * 2; i < nrows * 64; i += 512) {
            int r = i >> 6, c = i & 63;
            __half2 hv = __floats2half2_rn(fmaxf(fb[r * 72 + c], 0.f),
                                           fmaxf(fb[r * 72 + c + 1], 0.f));
            *(__half2*)&g_eh[(pb + r) * 64 + c] = hv;
        }
    }
}

// ---------------- attention: warp per node, 4-edge unroll, v prefetch ------
__device__ __forceinline__ float dot4(float4 a, float4 b) {
    return a.x * b.x + a.y * b.y + a.z * b.z + a.w * b.w;
}
__device__ __forceinline__ void ldh8(const __half* p, float4& a, float4& b) {
    uint4 u = *(const uint4*)p;
    float2 f0 = __half22float2(*(__half2*)&u.x);
    float2 f1 = __half22float2(*(__half2*)&u.y);
    float2 f2 = __half22float2(*(__half2*)&u.z);
    float2 f3 = __half22float2(*(__half2*)&u.w);
    a = make_float4(f0.x, f0.y, f1.x, f1.y);
    b = make_float4(f2.x, f2.y, f3.x, f3.y);
}

__global__ void __launch_bounds__(256) k_attn(int n) {
    int gw = (blockIdx.x * blockDim.x + threadIdx.x) >> 5;
    int lane = threadIdx.x & 31;
    if (gw >= n) return;
    int node = gw;
    int beg = g_rowptr[node], end = g_rowptr[node + 1];

    int h = lane >> 3;
    int c8 = (lane & 7) * 8;
    int chan = h * 64 + c8;

    float4 q0 = *(const float4*)&g_q[node * HC + chan];
    float4 q1 = *(const float4*)&g_q[node * HC + chan + 4];
    float4 gg0 = *(const float4*)&g_g[node * HC + chan];
    float4 gg1 = *(const float4*)&g_g[node * HC + chan + 4];
    float qb = g_qb[node * 4 + h];

    float s = 0.f;
    float4 av0 = {0,0,0,0}, av1 = {0,0,0,0};
    float4 at0 = {0,0,0,0}, at1 = {0,0,0,0};

    int p = beg;
    for (; p + 4 <= end; p += 4) {
        int src[4];
        #pragma unroll
        for (int u = 0; u < 4; u++) src[u] = g_src[p + u];

        float d[4];
        float4 e0[4], e1[4], v0[4], v1[4];
        #pragma unroll
        for (int u = 0; u < 4; u++) {
            float4 k0, k1;
            ldh8(&g_kh[src[u] * HC + chan], k0, k1);
            ldh8(&g_eh[(p + u) * 64 + c8], e0[u], e1[u]);
            ldh8(&g_vh[src[u] * HC + chan], v0[u], v1[u]);   // prefetch: overlaps shuffles
            d[u] = dot4(q0, k0) + dot4(q1, k1) + dot4(gg0, e0[u]) + dot4(gg1, e1[u]);
        }
        #pragma unroll
        for (int off = 1; off < 8; off <<= 1) {
            #pragma unroll
            for (int u = 0; u < 4; u++)
                d[u] += __shfl_xor_sync(0xffffffffu, d[u], off);
        }
        float pe[4];
        #pragma unroll
        for (int u = 0; u < 4; u++) {
            pe[u] = __expf((d[u] + qb) * 0.125f);
            s += pe[u];
        }
        #pragma unroll
        for (int u = 0; u < 4; u++) {
            av0.x += pe[u] * v0[u].x;  av0.y += pe[u] * v0[u].y;
            av0.z += pe[u] * v0[u].z;  av0.w += pe[u] * v0[u].w;
            av1.x += pe[u] * v1[u].x;  av1.y += pe[u] * v1[u].y;
            av1.z += pe[u] * v1[u].z;  av1.w += pe[u] * v1[u].w;
            at0.x += pe[u] * e0[u].x;  at0.y += pe[u] * e0[u].y;
            at0.z += pe[u] * e0[u].z;  at0.w += pe[u] * e0[u].w;
            at1.x += pe[u] * e1[u].x;  at1.y += pe[u] * e1[u].y;
            at1.z += pe[u] * e1[u].z;  at1.w += pe[u] * e1[u].w;
        }
    }
    for (; p < end; p++) {
        int src = g_src[p];
        float4 k0, k1, e0, e1, v0, v1;
        ldh8(&g_kh[src * HC + chan], k0, k1);
        ldh8(&g_eh[p * 64 + c8],     e0, e1);
        ldh8(&g_vh[src * HC + chan], v0, v1);
        float d = dot4(q0, k0) + dot4(q1, k1) + dot4(gg0, e0) + dot4(gg1, e1);
        d += __shfl_xor_sync(0xffffffffu, d, 1);
        d += __shfl_xor_sync(0xffffffffu, d, 2);
        d += __shfl_xor_sync(0xffffffffu, d, 4);
        float pe = __expf((d + qb) * 0.125f);
        s += pe;
        av0.x += pe * v0.x; av0.y += pe * v0.y; av0.z += pe * v0.z; av0.w += pe * v0.w;
        av1.x += pe * v1.x; av1.y += pe * v1.y; av1.z += pe * v1.z; av1.w += pe * v1.w;
        at0.x += pe * e0.x; at0.y += pe * e0.y; at0.z += pe * e0.z; at0.w += pe * e0.w;
        at1.x += pe * e1.x; at1.y += pe * e1.y; at1.z += pe * e1.z; at1.w += pe * e1.w;
    }

    float sinv = 1.f / (s + 1e-16f);
    float4 o0 = {av0.x * sinv, av0.y * sinv, av0.z * sinv, av0.w * sinv};
    float4 o1 = {av1.x * sinv, av1.y * sinv, av1.z * sinv, av1.w * sinv};
    float4 t0 = {at0.x * sinv, at0.y * sinv, at0.z * sinv, at0.w * sinv};
    float4 t1 = {at1.x * sinv, at1.y * sinv, at1.z * sinv, at1.w * sinv};
    *(float4*)&g_outv[node * HC + chan]     = o0;
    *(float4*)&g_outv[node * HC + chan + 4] = o1;
    *(float4*)&g_t   [node * HC + chan]     = t0;
    *(float4*)&g_t   [node * HC + chan + 4] = t1;
    if ((lane & 7) == 0) g_suma[node * 4 + h] = s * sinv;
}

// ---------------- fused epilogue: combine + LN + relu + head + logsoftmax --
__global__ void k_posthead(const float* __restrict__ wedge, const float* __restrict__ bedge,
                           const float* __restrict__ ln_g, const float* __restrict__ ln_b,
                           const float* __restrict__ w1, const float* __restrict__ b1,
                           const float* __restrict__ w2, const float* __restrict__ b2,
                           float* __restrict__ out, int n) {
    __shared__ float ts[16 * HC];   // t values, later reused for activations
    __shared__ float os[16 * HC];
    __shared__ float hs[16 * 128];
    __shared__ float ls[16][NCLS];
    int tid = threadIdx.x;
    int nb = blockIdx.x * 16;
    for (int i = tid; i < 16 * HC; i += 256) {
        int nn = nb + (i >> 8);
        ts[i] = (nn < n) ? g_t[nn * HC + (i & 255)] : 0.f;
    }
    __syncthreads();

    // t @ wedge (per-head) + combine
    int h = tid >> 6;
    float acc[16];
    #pragma unroll
    for (int m = 0; m < 16; m++) acc[m] = 0.f;
    for (int i = 0; i < 64; i++) {
        float w = __ldg(&wedge[i * HC + tid]);
        #pragma unroll
        for (int m = 0; m < 16; m++) acc[m] += ts[m * HC + h * 64 + i] * w;
    }
    float be = __ldg(&bedge[tid]);
    #pragma unroll
    for (int m = 0; m < 16; m++) {
        int nn = nb + m;
        if (nn < n) {
            os[m * HC + tid] = g_outv[nn * HC + tid] + g_suma[nn * 4 + h] * be
                             + g_skip[nn * HC + tid] + acc[m];
        }
    }
    __syncthreads();

    // LayerNorm + relu -> ts (reuse)
    int wid = tid >> 5, lane = tid & 31;
    for (int m = wid; m < 16; m += 8) {
        int nn = nb + m;
        if (nn >= n) continue;
        float sum = 0.f, sq = 0.f;
        #pragma unroll
        for (int u = 0; u < 8; u++) {
            float v = os[m * HC + u * 32 + lane];
            sum += v; sq += v * v;
        }
        #pragma unroll
        for (int off = 16; off; off >>= 1) {
            sum += __shfl_xor_sync(0xffffffffu, sum, off);
            sq  += __shfl_xor_sync(0xffffffffu, sq,  off);
        }
        float mu = sum * (1.f / 256.f);
        float var = sq * (1.f / 256.f) - mu * mu;
        float rs = rsqrtf(var + 1e-5f);
        #pragma unroll
        for (int u = 0; u < 8; u++) {
            int j = u * 32 + lane;
            float v = (os[m * HC + j] - mu) * rs * __ldg(&ln_g[j]) + __ldg(&ln_b[j]);
            ts[m * HC + j] = fmaxf(v, 0.f);
        }
    }
    __syncthreads();

    // head layer 1: [16 x 256] @ [256 x 128]
    {
        int col = tid & 127, rg = tid >> 7;   // rg 0/1 -> rows 0-7 / 8-15
        float a8[8];
        float bb = __ldg(&b1[col]);
        #pragma unroll
        for (int r = 0; r < 8; r++) a8[r] = bb;
        for (int i = 0; i < HC; i++) {
            float w = __ldg(&w1[i * 128 + col]);
            #pragma unroll
            for (int r = 0; r < 8; r++) a8[r] += ts[(rg * 8 + r) * HC + i] * w;
        }
        #pragma unroll
        for (int r = 0; r < 8; r++) hs[(rg * 8 + r) * 128 + col] = fmaxf(a8[r], 0.f);
    }
    __syncthreads();

    // head layer 2 + log_softmax
    if (tid < 64) {
        int m = tid >> 2, c = tid & 3;
        float a = __ldg(&b2[c]);
        for (int i = 0; i < 128; i++) a += hs[m * 128 + i] * __ldg(&w2[i * NCLS + c]);
        ls[m][c] = a;
    }
    __syncthreads();
    if (tid < 16) {
        int nn = nb + tid;
        if (nn < n) {
            float l0 = ls[tid][0], l1 = ls[tid][1], l2 = ls[tid][2], l3 = ls[tid][3];
            float mx = fmaxf(fmaxf(l0, l1), fmaxf(l2, l3));
            float se = expf(l0 - mx) + expf(l1 - mx) + expf(l2 - mx) + expf(l3 - mx);
            float lse = mx + logf(se);
            out[nn * NCLS + 0] = l0 - lse;
            out[nn * NCLS + 1] = l1 - lse;
            out[nn * NCLS + 2] = l2 - lse;
            out[nn * NCLS + 3] = l3 - lse;
        }
    }
}

// ---------------- launcher ----------------
extern "C" void kernel_launch(void* const* d_in, const int* in_sizes, int n_in,
                              void* d_out, int out_size) {
    const float* x     = (const float*)d_in[0];
    const int*   ei    = (const int*)  d_in[1];
    const float* eattr = (const float*)d_in[2];
    const float* w00   = (const float*)d_in[3];
    const float* b00   = (const float*)d_in[4];
    const float* we1   = (const float*)d_in[5];
    const float* be1   = (const float*)d_in[6];
    const float* we2   = (const float*)d_in[7];
    const float* be2   = (const float*)d_in[8];
    const float* we3   = (const float*)d_in[9];
    const float* be3   = (const float*)d_in[10];
    const float* wq    = (const float*)d_in[11];
    const float* bq    = (const float*)d_in[12];
    const float* wk    = (const float*)d_in[13];
    const float* bk    = (const float*)d_in[14];
    const float* wv    = (const float*)d_in[15];
    const float* bv    = (const float*)d_in[16];
    const float* wedge = (const float*)d_in[17];
    const float* bedge = (const float*)d_in[18];
    const float* wskip = (const float*)d_in[19];
    const float* bskip = (const float*)d_in[20];
    const float* ln_g  = (const float*)d_in[21];
    const float* ln_b  = (const float*)d_in[22];
    const float* w1    = (const float*)d_in[23];
    const float* b1    = (const float*)d_in[24];
    const float* w2    = (const float*)d_in[25];
    const float* b2    = (const float*)d_in[26];
    float* out = (float*)d_out;

    int n = in_sizes[0] / NFEAT;
    int e = in_sizes[1] / 2;

    static const int EDGE_SMEM = 111360;
    static const int PROJ_SMEM = (5632 + 21120) * 2;
    cudaFuncSetAttribute(k_edgemlp, cudaFuncAttributeMaxDynamicSharedMemorySize, EDGE_SMEM);
    cudaFuncSetAttribute(k_proj,    cudaFuncAttributeMaxDynamicSharedMemorySize, PROJ_SMEM);

    k_zero_deg<<<(n + 255) / 256, 256>>>(n);
    k_hist<<<(e + 255) / 256, 256>>>(ei, e);
    k_scan<<<1, 1024>>>(n);
    k_scatter<<<(e + 255) / 256, 256>>>(ei, e);
    k_wtt<<<64, 256>>>(wedge);

    k_node_embed<<<(n + 63) / 64, 256>>>(x, w00, b00, n);
    {
        dim3 grid((n + 63) / 64, 4);
        k_proj<<<grid, 256, PROJ_SMEM>>>(wq, bq, wk, bk, wv, bv, wskip, bskip, n);
    }
    k_g<<<(n + 31) / 32, 256>>>(bedge, n);

    k_edgemlp<<<(e + 127) / 128, 256, EDGE_SMEM>>>(eattr, we1, be1, we2, be2, we3, be3, e);

    k_attn<<<(n + 7) / 8, 256>>>(n);

    k_posthead<<<(n + 15) / 16, 256>>>(wedge, bedge, ln_g, ln_b, w1, b1, w2, b2, out, n);
}